// round 2
// baseline (speedup 1.0000x reference)
#include <cuda_runtime.h>

#define NB 16
#define NL 1024
#define NDIN 512
#define NH 8
#define MROWS (NB*NL)   // 16384

// ---------------- scratch (device globals: no allocation allowed) ----------------
__device__ float g_mu[3][MROWS];
__device__ float g_rstd[3][MROWS];
__device__ float g_Q[NB*NH*NL*64];      // [b,h,l,d]  32MB
__device__ float g_K[NB*NH*NL*64];
__device__ float g_V[NB*NH*NL*64];
__device__ float g_att[MROWS*NDIN];     // attention output, [b*l, h*64+d] 32MB

// ---------------- LayerNorm row statistics ----------------
__global__ __launch_bounds__(256) void ln_stats_kernel(
    const float* __restrict__ q, const float* __restrict__ k, const float* __restrict__ v)
{
    int warp = threadIdx.x >> 5, lane = threadIdx.x & 31;
    int row = blockIdx.x * 8 + warp;
    int t = blockIdx.y;
    const float* x = (t == 0 ? q : (t == 1 ? k : v)) + (size_t)row * NDIN;
    const float4* x4 = (const float4*)x;
    float s = 0.f, ss = 0.f;
    #pragma unroll
    for (int i = 0; i < 4; i++) {
        float4 a = x4[lane + 32 * i];
        s  += a.x + a.y + a.z + a.w;
        ss += a.x*a.x + a.y*a.y + a.z*a.z + a.w*a.w;
    }
    #pragma unroll
    for (int o = 16; o; o >>= 1) {
        s  += __shfl_xor_sync(0xffffffffu, s, o);
        ss += __shfl_xor_sync(0xffffffffu, ss, o);
    }
    if (lane == 0) {
        float mu = s * (1.f / 512.f);
        float var = ss * (1.f / 512.f) - mu * mu;
        g_mu[t][row] = mu;
        g_rstd[t][row] = rsqrtf(var + 1e-5f);
    }
}

// ---------------- projection GEMM: C = LN(x) @ W^T, writes [b,h,l,d] ----------------
// M=16384, N=512, K=512.  BM=BN=128, BK=16, 256 threads, 8x8 micro-tile.
__global__ __launch_bounds__(256, 2) void gemm_proj_kernel(
    const float* __restrict__ q, const float* __restrict__ k, const float* __restrict__ v,
    const float* __restrict__ Wq, const float* __restrict__ Wk, const float* __restrict__ Wv,
    const float* __restrict__ g1, const float* __restrict__ b1,
    const float* __restrict__ g2, const float* __restrict__ b2,
    const float* __restrict__ g3, const float* __restrict__ b3)
{
    int t = blockIdx.z;
    const float* A     = (t == 0) ? q  : (t == 1) ? k  : v;
    const float* W     = (t == 0) ? Wq : (t == 1) ? Wk : Wv;
    const float* gamma = (t == 0) ? g1 : (t == 1) ? g2 : g3;
    const float* beta  = (t == 0) ? b1 : (t == 1) ? b2 : b3;
    float* outp        = (t == 0) ? g_Q : (t == 1) ? g_K : g_V;

    __shared__ float As[16][128];
    __shared__ float Bs[16][128];
    __shared__ float sG[512], sB[512];

    int tid = threadIdx.x;
    int mr0 = blockIdx.y * 128;
    int nr0 = blockIdx.x * 128;

    for (int i = tid; i < 512; i += 256) { sG[i] = gamma[i]; sB[i] = beta[i]; }

    int mA = tid >> 2;            // 0..63
    int kq = (tid & 3) << 2;      // 0,4,8,12
    float mu0 = g_mu[t][mr0 + mA],      rs0 = g_rstd[t][mr0 + mA];
    float mu1 = g_mu[t][mr0 + mA + 64], rs1 = g_rstd[t][mr0 + mA + 64];

    int tr = tid >> 4, tc = tid & 15;
    float acc[8][8] = {};

    __syncthreads();  // sG/sB ready

    for (int kb = 0; kb < 512; kb += 16) {
        float4 x0 = *(const float4*)&A[(size_t)(mr0 + mA) * 512 + kb + kq];
        float4 x1 = *(const float4*)&A[(size_t)(mr0 + mA + 64) * 512 + kb + kq];
        float4 gv = *(const float4*)&sG[kb + kq];
        float4 bv = *(const float4*)&sB[kb + kq];
        x0.x = ((x0.x - mu0) * rs0) * gv.x + bv.x;
        x0.y = ((x0.y - mu0) * rs0) * gv.y + bv.y;
        x0.z = ((x0.z - mu0) * rs0) * gv.z + bv.z;
        x0.w = ((x0.w - mu0) * rs0) * gv.w + bv.w;
        x1.x = ((x1.x - mu1) * rs1) * gv.x + bv.x;
        x1.y = ((x1.y - mu1) * rs1) * gv.y + bv.y;
        x1.z = ((x1.z - mu1) * rs1) * gv.z + bv.z;
        x1.w = ((x1.w - mu1) * rs1) * gv.w + bv.w;
        As[kq + 0][mA] = x0.x; As[kq + 1][mA] = x0.y; As[kq + 2][mA] = x0.z; As[kq + 3][mA] = x0.w;
        As[kq + 0][mA + 64] = x1.x; As[kq + 1][mA + 64] = x1.y; As[kq + 2][mA + 64] = x1.z; As[kq + 3][mA + 64] = x1.w;

        float4 w0 = *(const float4*)&W[(size_t)(nr0 + mA) * 512 + kb + kq];
        float4 w1 = *(const float4*)&W[(size_t)(nr0 + mA + 64) * 512 + kb + kq];
        Bs[kq + 0][mA] = w0.x; Bs[kq + 1][mA] = w0.y; Bs[kq + 2][mA] = w0.z; Bs[kq + 3][mA] = w0.w;
        Bs[kq + 0][mA + 64] = w1.x; Bs[kq + 1][mA + 64] = w1.y; Bs[kq + 2][mA + 64] = w1.z; Bs[kq + 3][mA + 64] = w1.w;
        __syncthreads();

        #pragma unroll
        for (int kk = 0; kk < 16; kk++) {
            float4 a0 = *(const float4*)&As[kk][tr * 8];
            float4 a1 = *(const float4*)&As[kk][tr * 8 + 4];
            float4 c0 = *(const float4*)&Bs[kk][tc * 8];
            float4 c1 = *(const float4*)&Bs[kk][tc * 8 + 4];
            float aa[8] = {a0.x, a0.y, a0.z, a0.w, a1.x, a1.y, a1.z, a1.w};
            float bb[8] = {c0.x, c0.y, c0.z, c0.w, c1.x, c1.y, c1.z, c1.w};
            #pragma unroll
            for (int i = 0; i < 8; i++)
                #pragma unroll
                for (int j = 0; j < 8; j++)
                    acc[i][j] += aa[i] * bb[j];
        }
        __syncthreads();
    }

    int n0 = nr0 + tc * 8;
    int h = n0 >> 6, d = n0 & 63;
    #pragma unroll
    for (int i = 0; i < 8; i++) {
        int mr = mr0 + tr * 8 + i;
        int bb = mr >> 10, l = mr & 1023;
        float* p = outp + ((size_t)(bb * NH + h) << 16) + l * 64 + d;
        *(float4*)p       = make_float4(acc[i][0], acc[i][1], acc[i][2], acc[i][3]);
        *(float4*)(p + 4) = make_float4(acc[i][4], acc[i][5], acc[i][6], acc[i][7]);
    }
}

// ---------------- fc GEMM: dynamic = g_att @ Wfc^T ----------------
__global__ __launch_bounds__(256, 2) void gemm_fc_kernel(
    const float* __restrict__ Wfc, float* __restrict__ dyn)
{
    __shared__ float As[16][128];
    __shared__ float Bs[16][128];

    int tid = threadIdx.x;
    int mr0 = blockIdx.y * 128;
    int nr0 = blockIdx.x * 128;
    int mA = tid >> 2;
    int kq = (tid & 3) << 2;
    int tr = tid >> 4, tc = tid & 15;
    float acc[8][8] = {};
    const float* A = g_att;

    for (int kb = 0; kb < 512; kb += 16) {
        float4 x0 = *(const float4*)&A[(size_t)(mr0 + mA) * 512 + kb + kq];
        float4 x1 = *(const float4*)&A[(size_t)(mr0 + mA + 64) * 512 + kb + kq];
        As[kq + 0][mA] = x0.x; As[kq + 1][mA] = x0.y; As[kq + 2][mA] = x0.z; As[kq + 3][mA] = x0.w;
        As[kq + 0][mA + 64] = x1.x; As[kq + 1][mA + 64] = x1.y; As[kq + 2][mA + 64] = x1.z; As[kq + 3][mA + 64] = x1.w;
        float4 w0 = *(const float4*)&Wfc[(size_t)(nr0 + mA) * 512 + kb + kq];
        float4 w1 = *(const float4*)&Wfc[(size_t)(nr0 + mA + 64) * 512 + kb + kq];
        Bs[kq + 0][mA] = w0.x; Bs[kq + 1][mA] = w0.y; Bs[kq + 2][mA] = w0.z; Bs[kq + 3][mA] = w0.w;
        Bs[kq + 0][mA + 64] = w1.x; Bs[kq + 1][mA + 64] = w1.y; Bs[kq + 2][mA + 64] = w1.z; Bs[kq + 3][mA + 64] = w1.w;
        __syncthreads();
        #pragma unroll
        for (int kk = 0; kk < 16; kk++) {
            float4 a0 = *(const float4*)&As[kk][tr * 8];
            float4 a1 = *(const float4*)&As[kk][tr * 8 + 4];
            float4 c0 = *(const float4*)&Bs[kk][tc * 8];
            float4 c1 = *(const float4*)&Bs[kk][tc * 8 + 4];
            float aa[8] = {a0.x, a0.y, a0.z, a0.w, a1.x, a1.y, a1.z, a1.w};
            float bb[8] = {c0.x, c0.y, c0.z, c0.w, c1.x, c1.y, c1.z, c1.w};
            #pragma unroll
            for (int i = 0; i < 8; i++)
                #pragma unroll
                for (int j = 0; j < 8; j++)
                    acc[i][j] += aa[i] * bb[j];
        }
        __syncthreads();
    }

    #pragma unroll
    for (int i = 0; i < 8; i++) {
        float* p = dyn + (size_t)(mr0 + tr * 8 + i) * 512 + nr0 + tc * 8;
        *(float4*)p       = make_float4(acc[i][0], acc[i][1], acc[i][2], acc[i][3]);
        *(float4*)(p + 4) = make_float4(acc[i][4], acc[i][5], acc[i][6], acc[i][7]);
    }
}

// ---------------- fused attention: scores + masked softmax + attn write + PV ----------------
// grid (32 qblocks, 8 heads, 16 batch), 256 threads, 1 CTA handles 32 q-rows.
__global__ __launch_bounds__(256, 1) void attn_kernel(
    const int* __restrict__ mask, float* __restrict__ attn_out)
{
    extern __shared__ float sm[];
    float* Ssc = sm;                    // [32][1024]
    float* Qt  = sm + 32 * 1024;        // [64][40]  (d-major Q tile)
    float* KVt = Qt + 64 * 40;          // [64][68]  (K: d-major; V: k-major)

    int tid = threadIdx.x;
    int q0 = blockIdx.x * 32;
    int h = blockIdx.y, b = blockIdx.z;
    size_t bh = (size_t)(b * NH + h);
    const float* Qg = g_Q + (bh << 16) + (size_t)q0 * 64;
    const float* Kg = g_K + (bh << 16);
    const float* Vg = g_V + (bh << 16);

    // load Q tile transposed: Qt[d][r]
    {
        int r = tid >> 3;
        int dq = (tid & 7) * 8;
        float4 v0 = *(const float4*)&Qg[r * 64 + dq];
        float4 v1 = *(const float4*)&Qg[r * 64 + dq + 4];
        Qt[(dq + 0) * 40 + r] = v0.x; Qt[(dq + 1) * 40 + r] = v0.y;
        Qt[(dq + 2) * 40 + r] = v0.z; Qt[(dq + 3) * 40 + r] = v0.w;
        Qt[(dq + 4) * 40 + r] = v1.x; Qt[(dq + 5) * 40 + r] = v1.y;
        Qt[(dq + 6) * 40 + r] = v1.z; Qt[(dq + 7) * 40 + r] = v1.w;
    }

    int cp = tid & 31, rq = tid >> 5;
    int c0 = cp * 2;

    // ---- pass 1: S = Q K^T / 8 into Ssc ----
    for (int kt = 0; kt < 16; kt++) {
        __syncthreads();
        {
            int c = tid >> 2, f = tid & 3;
            const float* src = &Kg[(kt * 64 + c) * 64];
            #pragma unroll
            for (int jj = 0; jj < 4; jj++) {
                int d0 = f * 16 + jj * 4;
                float4 kv = *(const float4*)&src[d0];
                KVt[(d0 + 0) * 68 + c] = kv.x;
                KVt[(d0 + 1) * 68 + c] = kv.y;
                KVt[(d0 + 2) * 68 + c] = kv.z;
                KVt[(d0 + 3) * 68 + c] = kv.w;
            }
        }
        __syncthreads();
        float a00 = 0, a01 = 0, a10 = 0, a11 = 0, a20 = 0, a21 = 0, a30 = 0, a31 = 0;
        #pragma unroll
        for (int d = 0; d < 64; d++) {
            float2 kv = *(const float2*)&KVt[d * 68 + c0];
            float4 qv = *(const float4*)&Qt[d * 40 + rq * 4];
            a00 += qv.x * kv.x; a01 += qv.x * kv.y;
            a10 += qv.y * kv.x; a11 += qv.y * kv.y;
            a20 += qv.z * kv.x; a21 += qv.z * kv.y;
            a30 += qv.w * kv.x; a31 += qv.w * kv.y;
        }
        const float sc = 0.125f;
        int col = kt * 64 + c0;
        *(float2*)&Ssc[(rq * 4 + 0) * 1024 + col] = make_float2(a00 * sc, a01 * sc);
        *(float2*)&Ssc[(rq * 4 + 1) * 1024 + col] = make_float2(a10 * sc, a11 * sc);
        *(float2*)&Ssc[(rq * 4 + 2) * 1024 + col] = make_float2(a20 * sc, a21 * sc);
        *(float2*)&Ssc[(rq * 4 + 3) * 1024 + col] = make_float2(a30 * sc, a31 * sc);
    }
    __syncthreads();

    // ---- masked softmax (exact reference algebra) + attn write ----
    {
        int warp = tid >> 5, lane = tid & 31;
        for (int rr = 0; rr < 4; rr++) {
            int r = warp * 4 + rr;
            int qg = q0 + r;
            const int* mrow = mask + ((size_t)b * 1024 + qg) * 1024;
            float* srow = &Ssc[r * 1024];
            float mx = 0.f; int cnt = 0;   // masked entries have t=0, so true max >= 0
            for (int kk = lane; kk < 1024; kk += 32) {
                float s = srow[kk];
                int mk = mrow[kk];
                bool allowed = (kk != qg) && (mk == 0);
                float tt = allowed ? s : 0.f;
                srow[kk] = tt;
                cnt += allowed ? 0 : 1;
                mx = fmaxf(mx, tt);
            }
            #pragma unroll
            for (int o = 16; o; o >>= 1) {
                mx = fmaxf(mx, __shfl_xor_sync(0xffffffffu, mx, o));
                cnt += __shfl_xor_sync(0xffffffffu, cnt, o);
            }
            float sum = 0.f;
            for (int kk = lane; kk < 1024; kk += 32) {
                float tt = srow[kk];
                float e = (tt != 0.f) ? __expf(tt - mx) : 0.f;
                srow[kk] = e;
                sum += e;
            }
            #pragma unroll
            for (int o = 16; o; o >>= 1) sum += __shfl_xor_sync(0xffffffffu, sum, o);
            float Z = sum + (float)cnt * __expf(-mx);     // full softmax denominator
            float inv = 1.f / (sum + 1e-13f * Z);
            float* orow = attn_out + (((size_t)h * NB + b) * 1024 + qg) * 1024;
            for (int kk = lane; kk < 1024; kk += 32) {
                float a = srow[kk] * inv;
                srow[kk] = a;
                orow[kk] = a;
            }
        }
    }

    // ---- pass 2: out = attn @ V ----
    int dv0 = c0;
    float o00 = 0, o01 = 0, o10 = 0, o11 = 0, o20 = 0, o21 = 0, o30 = 0, o31 = 0;
    for (int kt = 0; kt < 16; kt++) {
        __syncthreads();
        {
            int kk = tid >> 2, f = tid & 3;
            const float* src = &Vg[(kt * 64 + kk) * 64];
            #pragma unroll
            for (int jj = 0; jj < 4; jj++) {
                int d0 = f * 16 + jj * 4;
                *(float4*)&KVt[kk * 68 + d0] = *(const float4*)&src[d0];
            }
        }
        __syncthreads();
        const float* s0 = &Ssc[(rq * 4 + 0) * 1024 + kt * 64];
        const float* s1 = s0 + 1024;
        const float* s2 = s1 + 1024;
        const float* s3 = s2 + 1024;
        #pragma unroll
        for (int kk = 0; kk < 64; kk += 4) {
            float4 a0 = *(const float4*)&s0[kk];
            float4 a1 = *(const float4*)&s1[kk];
            float4 a2 = *(const float4*)&s2[kk];
            float4 a3 = *(const float4*)&s3[kk];
            float2 v0 = *(const float2*)&KVt[(kk + 0) * 68 + dv0];
            float2 v1 = *(const float2*)&KVt[(kk + 1) * 68 + dv0];
            float2 v2 = *(const float2*)&KVt[(kk + 2) * 68 + dv0];
            float2 v3 = *(const float2*)&KVt[(kk + 3) * 68 + dv0];
            o00 += a0.x * v0.x; o01 += a0.x * v0.y;
            o10 += a1.x * v0.x; o11 += a1.x * v0.y;
            o20 += a2.x * v0.x; o21 += a2.x * v0.y;
            o30 += a3.x * v0.x; o31 += a3.x * v0.y;
            o00 += a0.y * v1.x; o01 += a0.y * v1.y;
            o10 += a1.y * v1.x; o11 += a1.y * v1.y;
            o20 += a2.y * v1.x; o21 += a2.y * v1.y;
            o30 += a3.y * v1.x; o31 += a3.y * v1.y;
            o00 += a0.z * v2.x; o01 += a0.z * v2.y;
            o10 += a1.z * v2.x; o11 += a1.z * v2.y;
            o20 += a2.z * v2.x; o21 += a2.z * v2.y;
            o30 += a3.z * v2.x; o31 += a3.z * v2.y;
            o00 += a0.w * v3.x; o01 += a0.w * v3.y;
            o10 += a1.w * v3.x; o11 += a1.w * v3.y;
            o20 += a2.w * v3.x; o21 += a2.w * v3.y;
            o30 += a3.w * v3.x; o31 += a3.w * v3.y;
        }
    }
    {
        size_t base = ((size_t)b * 1024 + q0 + rq * 4) * 512 + h * 64 + dv0;
        *(float2*)&g_att[base          ] = make_float2(o00, o01);
        *(float2*)&g_att[base + 512    ] = make_float2(o10, o11);
        *(float2*)&g_att[base + 1024   ] = make_float2(o20, o21);
        *(float2*)&g_att[base + 1536   ] = make_float2(o30, o31);
    }
}

// ---------------- launch ----------------
extern "C" void kernel_launch(void* const* d_in, const int* in_sizes, int n_in,
                              void* d_out, int out_size)
{
    (void)in_sizes; (void)n_in; (void)out_size;
    const float* q   = (const float*)d_in[0];
    const float* k   = (const float*)d_in[1];
    const float* v   = (const float*)d_in[2];
    const int*   msk = (const int*)d_in[3];
    const float* Wq  = (const float*)d_in[4];
    const float* Wk  = (const float*)d_in[5];
    const float* Wv  = (const float*)d_in[6];
    const float* Wfc = (const float*)d_in[7];
    const float* g1  = (const float*)d_in[8];
    const float* b1  = (const float*)d_in[9];
    const float* g2  = (const float*)d_in[10];
    const float* b2  = (const float*)d_in[11];
    const float* g3  = (const float*)d_in[12];
    const float* b3  = (const float*)d_in[13];

    float* out = (float*)d_out;
    float* dyn_out  = out;                            // [16,1024,512]
    float* attn_out = out + (size_t)MROWS * 512;      // [128,1024,1024]

    const int attn_smem = (32 * 1024 + 64 * 40 + 64 * 68) * 4;  // 158720 B
    cudaFuncSetAttribute(attn_kernel, cudaFuncAttributeMaxDynamicSharedMemorySize, attn_smem);

    ln_stats_kernel<<<dim3(2048, 3), 256>>>(q, k, v);
    gemm_proj_kernel<<<dim3(4, 128, 3), 256>>>(q, k, v, Wq, Wk, Wv, g1, b1, g2, b2, g3, b3);
    attn_kernel<<<dim3(32, 8, 16), 256, attn_smem>>>(msk, attn_out);
    gemm_fc_kernel<<<dim3(4, 128), 256>>>(Wfc, dyn_out);
}

// round 4
// speedup vs baseline: 1.1695x; 1.1695x over previous
#include <cuda_runtime.h>
#include <cuda_bf16.h>

#define NB 16
#define NL 1024
#define NDIN 512
#define NH 8
#define MROWS (NB*NL)   // 16384

// ---------------- scratch (device globals: no allocation allowed) ----------------
__device__ float g_mu[3][MROWS];
__device__ float g_rstd[3][MROWS];
__device__ __align__(16) float g_Q[NB*NH*NL*64];      // [b,h,l,d]  32MB
__device__ __align__(16) float g_K[NB*NH*NL*64];
__device__ __align__(16) float g_V[NB*NH*NL*64];
__device__ __align__(16) __nv_bfloat16 g_Ah[3][MROWS*512];   // LN(x) hi
__device__ __align__(16) __nv_bfloat16 g_Al[3][MROWS*512];   // LN(x) lo
__device__ __align__(16) __nv_bfloat16 g_Wh[4][512*512];     // Wq,Wk,Wv,Wfc hi
__device__ __align__(16) __nv_bfloat16 g_Wl[4][512*512];
__device__ __align__(16) __nv_bfloat16 g_atth[MROWS*512];    // attn concat out hi
__device__ __align__(16) __nv_bfloat16 g_attl[MROWS*512];

// ---------------- helpers ----------------
__device__ __forceinline__ unsigned smem_u32(const void* p) {
    unsigned a;
    asm("{ .reg .u64 t; cvta.to.shared.u64 t, %1; cvt.u32.u64 %0, t; }" : "=r"(a) : "l"(p));
    return a;
}
__device__ __forceinline__ void cp16(unsigned dst, const void* src) {
    asm volatile("cp.async.cg.shared.global [%0], [%1], 16;" :: "r"(dst), "l"(src));
}
__device__ __forceinline__ void ldm4(unsigned& r0, unsigned& r1, unsigned& r2, unsigned& r3, unsigned a) {
    asm volatile("ldmatrix.sync.aligned.m8n8.x4.shared.b16 {%0,%1,%2,%3}, [%4];"
                 : "=r"(r0), "=r"(r1), "=r"(r2), "=r"(r3) : "r"(a));
}
__device__ __forceinline__ void mma_bf16(float* d, const unsigned* a, unsigned b0, unsigned b1) {
    asm volatile(
        "mma.sync.aligned.m16n8k16.row.col.f32.bf16.bf16.f32 "
        "{%0,%1,%2,%3}, {%4,%5,%6,%7}, {%8,%9}, {%0,%1,%2,%3};"
        : "+f"(d[0]), "+f"(d[1]), "+f"(d[2]), "+f"(d[3])
        : "r"(a[0]), "r"(a[1]), "r"(a[2]), "r"(a[3]), "r"(b0), "r"(b1));
}
__device__ __forceinline__ void split_hl(float y, __nv_bfloat16& h, __nv_bfloat16& l) {
    h = __float2bfloat16(y);
    l = __float2bfloat16(y - __bfloat162float(h));
}
__device__ __forceinline__ void store_hl2(__nv_bfloat16* ph, __nv_bfloat16* pl, float a, float b) {
    __nv_bfloat162 H, L;
    split_hl(a, H.x, L.x);
    split_hl(b, H.y, L.y);
    *(__nv_bfloat162*)ph = H;
    *(__nv_bfloat162*)pl = L;
}

// ---------------- LayerNorm row statistics ----------------
__global__ __launch_bounds__(256) void ln_stats_kernel(
    const float* __restrict__ q, const float* __restrict__ k, const float* __restrict__ v)
{
    int warp = threadIdx.x >> 5, lane = threadIdx.x & 31;
    int row = blockIdx.x * 8 + warp;
    int t = blockIdx.y;
    const float* x = (t == 0 ? q : (t == 1 ? k : v)) + (size_t)row * NDIN;
    const float4* x4 = (const float4*)x;
    float s = 0.f, ss = 0.f;
    #pragma unroll
    for (int i = 0; i < 4; i++) {
        float4 a = x4[lane + 32 * i];
        s  += a.x + a.y + a.z + a.w;
        ss += a.x*a.x + a.y*a.y + a.z*a.z + a.w*a.w;
    }
    #pragma unroll
    for (int o = 16; o; o >>= 1) {
        s  += __shfl_xor_sync(0xffffffffu, s, o);
        ss += __shfl_xor_sync(0xffffffffu, ss, o);
    }
    if (lane == 0) {
        float mu = s * (1.f / 512.f);
        float var = ss * (1.f / 512.f) - mu * mu;
        g_mu[t][row] = mu;
        g_rstd[t][row] = rsqrtf(var + 1e-5f);
    }
}

// ---------------- LN apply + bf16 hi/lo split ----------------
__global__ __launch_bounds__(256) void convert_ln_kernel(
    const float* __restrict__ q, const float* __restrict__ k, const float* __restrict__ v,
    const float* __restrict__ g1, const float* __restrict__ b1,
    const float* __restrict__ g2, const float* __restrict__ b2,
    const float* __restrict__ g3, const float* __restrict__ b3)
{
    int warp = threadIdx.x >> 5, lane = threadIdx.x & 31;
    int t = blockIdx.y;
    int row = blockIdx.x * 8 + warp;
    const float* x  = (t == 0 ? q  : (t == 1 ? k  : v))  + (size_t)row * 512;
    const float* G  = (t == 0 ? g1 : (t == 1 ? g2 : g3));
    const float* Bt = (t == 0 ? b1 : (t == 1 ? b2 : b3));
    float mu = g_mu[t][row], rs = g_rstd[t][row];
    __nv_bfloat16* ph = g_Ah[t] + (size_t)row * 512;
    __nv_bfloat16* pl = g_Al[t] + (size_t)row * 512;
    #pragma unroll
    for (int i = 0; i < 4; i++) {
        int c4 = lane + 32 * i;
        float4 xv = ((const float4*)x)[c4];
        float4 gv = ((const float4*)G)[c4];
        float4 bv = ((const float4*)Bt)[c4];
        float y[4];
        y[0] = (xv.x - mu) * rs * gv.x + bv.x;
        y[1] = (xv.y - mu) * rs * gv.y + bv.y;
        y[2] = (xv.z - mu) * rs * gv.z + bv.z;
        y[3] = (xv.w - mu) * rs * gv.w + bv.w;
        __nv_bfloat16 hh[4], ll[4];
        #pragma unroll
        for (int j = 0; j < 4; j++) split_hl(y[j], hh[j], ll[j]);
        *(uint2*)(ph + c4 * 4) = *(uint2*)hh;
        *(uint2*)(pl + c4 * 4) = *(uint2*)ll;
    }
}

// ---------------- W hi/lo split ----------------
__global__ __launch_bounds__(256) void convert_w_kernel(
    const float* __restrict__ Wq, const float* __restrict__ Wk,
    const float* __restrict__ Wv, const float* __restrict__ Wfc)
{
    int idx = (blockIdx.x * 256 + threadIdx.x) * 4;
    int mat = idx >> 18;
    int off = idx & 262143;
    const float* W = (mat == 0) ? Wq : ((mat == 1) ? Wk : ((mat == 2) ? Wv : Wfc));
    float4 xv = *(const float4*)(W + off);
    float y[4] = {xv.x, xv.y, xv.z, xv.w};
    __nv_bfloat16 hh[4], ll[4];
    #pragma unroll
    for (int j = 0; j < 4; j++) split_hl(y[j], hh[j], ll[j]);
    *(uint2*)(g_Wh[mat] + off) = *(uint2*)hh;
    *(uint2*)(g_Wl[mat] + off) = *(uint2*)ll;
}

// ---------------- mma.sync GEMM: C = A @ W^T (bf16 hi/lo 3-term) ----------------
// BM=BN=128, BK=32. Stage smem: Ah 8K | Al 8K | Bh 8K | Bl 8K = 32KB, 4 stages.
// Layout per version: [kc(2)][row(128)][16 bf16 = 2 x 16B chunks], chunk swizzled
// by (row>>2)&1 so ldmatrix.x4 phases are bank-conflict-free.
#define STG 32768
#define VOFF_AL 8192
#define VOFF_BH 16384
#define VOFF_BL 24576

__device__ __forceinline__ void load_stage_mma(
    const __nv_bfloat16* __restrict__ Ah, const __nv_bfloat16* __restrict__ Al,
    const __nv_bfloat16* __restrict__ Bh, const __nv_bfloat16* __restrict__ Bl,
    int mr0, int nr0, int kb, unsigned dstb, int tid)
{
    int m = tid >> 1;
    int c = tid & 1;
    unsigned dst0 = dstb + m * 32 + ((unsigned)(c ^ ((m >> 2) & 1)) << 4);
    size_t ga = (size_t)(mr0 + m) * 512 + kb + c * 8;
    size_t gb = (size_t)(nr0 + m) * 512 + kb + c * 8;
    #pragma unroll
    for (int kc = 0; kc < 2; kc++) {
        cp16(dst0 + kc * 4096,           Ah + ga + kc * 16);
        cp16(dst0 + kc * 4096 + VOFF_AL, Al + ga + kc * 16);
        cp16(dst0 + kc * 4096 + VOFF_BH, Bh + gb + kc * 16);
        cp16(dst0 + kc * 4096 + VOFF_BL, Bl + gb + kc * 16);
    }
    asm volatile("cp.async.commit_group;");
}

__global__ __launch_bounds__(256, 1) void gemm_mma_kernel(float* __restrict__ c_fc, int mode)
{
    extern __shared__ char smem[];
    unsigned sb = smem_u32(smem);
    int tid = threadIdx.x, wid = tid >> 5, lane = tid & 31;
    int z = blockIdx.z;
    int mr0 = blockIdx.y * 128;
    int nr0 = blockIdx.x * 128;

    const __nv_bfloat16 *Ah, *Al, *Wh, *Wl;
    float* outp;
    if (mode == 0) {
        Ah = g_Ah[z]; Al = g_Al[z]; Wh = g_Wh[z]; Wl = g_Wl[z];
        outp = (z == 0) ? g_Q : ((z == 1) ? g_K : g_V);
    } else {
        Ah = g_atth; Al = g_attl; Wh = g_Wh[3]; Wl = g_Wl[3];
        outp = c_fc;
    }

    // per-thread ldmatrix address offset (row-within-16-tile + swizzled chunk)
    int rA = (lane & 7) + ((lane >> 3) & 1) * 8;
    int chv = lane >> 4;
    unsigned offT = (unsigned)(rA * 32 + ((chv ^ ((rA >> 2) & 1)) << 4));
    int wm = wid >> 2, wn = wid & 3;   // warp tile: rows wm*64, cols wn*32

    float acc[4][4][4];
    #pragma unroll
    for (int a = 0; a < 4; a++)
        #pragma unroll
        for (int b = 0; b < 4; b++)
            #pragma unroll
            for (int c = 0; c < 4; c++) acc[a][b][c] = 0.f;

    // prologue: stages 0..2
    load_stage_mma(Ah, Al, Wh, Wl, mr0, nr0, 0,  sb,           tid);
    load_stage_mma(Ah, Al, Wh, Wl, mr0, nr0, 32, sb + STG,     tid);
    load_stage_mma(Ah, Al, Wh, Wl, mr0, nr0, 64, sb + 2 * STG, tid);

    #pragma unroll 1
    for (int s = 0; s < 16; s++) {
        asm volatile("cp.async.wait_group 2;");
        __syncthreads();
        unsigned buf = sb + (unsigned)(s & 3) * STG;

        #pragma unroll
        for (int kc = 0; kc < 2; kc++) {
            unsigned abase = buf + kc * 4096;
            unsigned bbase = buf + VOFF_BH + kc * 4096;
            unsigned aH[4][4], bH[2][4];
            #pragma unroll
            for (int mt = 0; mt < 4; mt++)
                ldm4(aH[mt][0], aH[mt][1], aH[mt][2], aH[mt][3],
                     abase + (unsigned)((wm * 64 + mt * 16) * 32) + offT);
            #pragma unroll
            for (int bt = 0; bt < 2; bt++)
                ldm4(bH[bt][0], bH[bt][1], bH[bt][2], bH[bt][3],
                     bbase + (unsigned)((wn * 32 + bt * 16) * 32) + offT);
            // pass 1: Ah * Bh
            #pragma unroll
            for (int mt = 0; mt < 4; mt++)
                #pragma unroll
                for (int nt = 0; nt < 4; nt++)
                    mma_bf16(acc[mt][nt], aH[mt], bH[nt >> 1][nt & 1], bH[nt >> 1][(nt & 1) + 2]);
            // pass 2: Ah * Bl
            {
                unsigned bL[2][4];
                #pragma unroll
                for (int bt = 0; bt < 2; bt++)
                    ldm4(bL[bt][0], bL[bt][1], bL[bt][2], bL[bt][3],
                         bbase + 8192 + (unsigned)((wn * 32 + bt * 16) * 32) + offT);
                #pragma unroll
                for (int mt = 0; mt < 4; mt++)
                    #pragma unroll
                    for (int nt = 0; nt < 4; nt++)
                        mma_bf16(acc[mt][nt], aH[mt], bL[nt >> 1][nt & 1], bL[nt >> 1][(nt & 1) + 2]);
            }
            // pass 3: Al * Bh
            {
                unsigned aL[4][4];
                #pragma unroll
                for (int mt = 0; mt < 4; mt++)
                    ldm4(aL[mt][0], aL[mt][1], aL[mt][2], aL[mt][3],
                         abase + VOFF_AL + (unsigned)((wm * 64 + mt * 16) * 32) + offT);
                #pragma unroll
                for (int mt = 0; mt < 4; mt++)
                    #pragma unroll
                    for (int nt = 0; nt < 4; nt++)
                        mma_bf16(acc[mt][nt], aL[mt], bH[nt >> 1][nt & 1], bH[nt >> 1][(nt & 1) + 2]);
            }
        }

        if (s + 3 < 16)
            load_stage_mma(Ah, Al, Wh, Wl, mr0, nr0, (s + 3) * 32, sb + (unsigned)((s + 3) & 3) * STG, tid);
        else
            asm volatile("cp.async.commit_group;");
    }

    // ---- epilogue ----
    int gr = lane >> 2, gc = (lane & 3) * 2;
    #pragma unroll
    for (int mt = 0; mt < 4; mt++) {
        #pragma unroll
        for (int nt = 0; nt < 4; nt++) {
            int r0 = mr0 + wm * 64 + mt * 16 + gr;
            int n0 = nr0 + wn * 32 + nt * 8 + gc;
            if (mode == 0) {
                int h = n0 >> 6, d = n0 & 63;
                int bb = r0 >> 10, li = r0 & 1023;
                float* p0 = outp + ((size_t)(bb * 8 + h) << 16) + (size_t)li * 64 + d;
                float* p1 = outp + ((size_t)(((r0 + 8) >> 10) * 8 + h) << 16) + (size_t)((r0 + 8) & 1023) * 64 + d;
                *(float2*)p0 = make_float2(acc[mt][nt][0], acc[mt][nt][1]);
                *(float2*)p1 = make_float2(acc[mt][nt][2], acc[mt][nt][3]);
            } else {
                float* p0 = outp + (size_t)r0 * 512 + n0;
                *(float2*)p0 = make_float2(acc[mt][nt][0], acc[mt][nt][1]);
                *(float2*)(p0 + 8 * 512) = make_float2(acc[mt][nt][2], acc[mt][nt][3]);
            }
        }
    }
}

// ---------------- fused attention: scores + masked softmax + attn write + PV ----------------
__global__ __launch_bounds__(256, 1) void attn_kernel(
    const int* __restrict__ mask, float* __restrict__ attn_out)
{
    extern __shared__ float sm[];
    float* Ssc = sm;                    // [32][1024]
    float* Qt  = sm + 32 * 1024;        // [64][40]
    float* KVt = Qt + 64 * 40;          // [64][68]

    int tid = threadIdx.x;
    int q0 = blockIdx.x * 32;
    int h = blockIdx.y, b = blockIdx.z;
    size_t bh = (size_t)(b * NH + h);
    const float* Qg = g_Q + (bh << 16) + (size_t)q0 * 64;
    const float* Kg = g_K + (bh << 16);
    const float* Vg = g_V + (bh << 16);

    {
        int r = tid >> 3;
        int dq = (tid & 7) * 8;
        float4 v0 = *(const float4*)&Qg[r * 64 + dq];
        float4 v1 = *(const float4*)&Qg[r * 64 + dq + 4];
        Qt[(dq + 0) * 40 + r] = v0.x; Qt[(dq + 1) * 40 + r] = v0.y;
        Qt[(dq + 2) * 40 + r] = v0.z; Qt[(dq + 3) * 40 + r] = v0.w;
        Qt[(dq + 4) * 40 + r] = v1.x; Qt[(dq + 5) * 40 + r] = v1.y;
        Qt[(dq + 6) * 40 + r] = v1.z; Qt[(dq + 7) * 40 + r] = v1.w;
    }

    int cp = tid & 31, rq = tid >> 5;
    int c0 = cp * 2;

    for (int kt = 0; kt < 16; kt++) {
        __syncthreads();
        {
            int c = tid >> 2, f = tid & 3;
            const float* src = &Kg[(kt * 64 + c) * 64];
            #pragma unroll
            for (int jj = 0; jj < 4; jj++) {
                int d0 = f * 16 + jj * 4;
                float4 kv = *(const float4*)&src[d0];
                KVt[(d0 + 0) * 68 + c] = kv.x;
                KVt[(d0 + 1) * 68 + c] = kv.y;
                KVt[(d0 + 2) * 68 + c] = kv.z;
                KVt[(d0 + 3) * 68 + c] = kv.w;
            }
        }
        __syncthreads();
        float a00 = 0, a01 = 0, a10 = 0, a11 = 0, a20 = 0, a21 = 0, a30 = 0, a31 = 0;
        #pragma unroll
        for (int d = 0; d < 64; d++) {
            float2 kv = *(const float2*)&KVt[d * 68 + c0];
            float4 qv = *(const float4*)&Qt[d * 40 + rq * 4];
            a00 += qv.x * kv.x; a01 += qv.x * kv.y;
            a10 += qv.y * kv.x; a11 += qv.y * kv.y;
            a20 += qv.z * kv.x; a21 += qv.z * kv.y;
            a30 += qv.w * kv.x; a31 += qv.w * kv.y;
        }
        const float sc = 0.125f;
        int col = kt * 64 + c0;
        *(float2*)&Ssc[(rq * 4 + 0) * 1024 + col] = make_float2(a00 * sc, a01 * sc);
        *(float2*)&Ssc[(rq * 4 + 1) * 1024 + col] = make_float2(a10 * sc, a11 * sc);
        *(float2*)&Ssc[(rq * 4 + 2) * 1024 + col] = make_float2(a20 * sc, a21 * sc);
        *(float2*)&Ssc[(rq * 4 + 3) * 1024 + col] = make_float2(a30 * sc, a31 * sc);
    }
    __syncthreads();

    {
        int warp = tid >> 5, lane = tid & 31;
        for (int rr = 0; rr < 4; rr++) {
            int r = warp * 4 + rr;
            int qg = q0 + r;
            const int* mrow = mask + ((size_t)b * 1024 + qg) * 1024;
            float* srow = &Ssc[r * 1024];
            float mx = 0.f; int cnt = 0;
            for (int kk = lane; kk < 1024; kk += 32) {
                float s = srow[kk];
                int mk = mrow[kk];
                bool allowed = (kk != qg) && (mk == 0);
                float tt = allowed ? s : 0.f;
                srow[kk] = tt;
                cnt += allowed ? 0 : 1;
                mx = fmaxf(mx, tt);
            }
            #pragma unroll
            for (int o = 16; o; o >>= 1) {
                mx = fmaxf(mx, __shfl_xor_sync(0xffffffffu, mx, o));
                cnt += __shfl_xor_sync(0xffffffffu, cnt, o);
            }
            float sum = 0.f;
            for (int kk = lane; kk < 1024; kk += 32) {
                float tt = srow[kk];
                float e = (tt != 0.f) ? __expf(tt - mx) : 0.f;
                srow[kk] = e;
                sum += e;
            }
            #pragma unroll
            for (int o = 16; o; o >>= 1) sum += __shfl_xor_sync(0xffffffffu, sum, o);
            float Z = sum + (float)cnt * __expf(-mx);
            float inv = 1.f / (sum + 1e-13f * Z);
            float* orow = attn_out + (((size_t)h * NB + b) * 1024 + qg) * 1024;
            for (int kk = lane; kk < 1024; kk += 32) {
                float a = srow[kk] * inv;
                srow[kk] = a;
                orow[kk] = a;
            }
        }
    }

    int dv0 = c0;
    float o00 = 0, o01 = 0, o10 = 0, o11 = 0, o20 = 0, o21 = 0, o30 = 0, o31 = 0;
    for (int kt = 0; kt < 16; kt++) {
        __syncthreads();
        {
            int kk = tid >> 2, f = tid & 3;
            const float* src = &Vg[(kt * 64 + kk) * 64];
            #pragma unroll
            for (int jj = 0; jj < 4; jj++) {
                int d0 = f * 16 + jj * 4;
                *(float4*)&KVt[kk * 68 + d0] = *(const float4*)&src[d0];
            }
        }
        __syncthreads();
        const float* s0 = &Ssc[(rq * 4 + 0) * 1024 + kt * 64];
        const float* s1 = s0 + 1024;
        const float* s2 = s1 + 1024;
        const float* s3 = s2 + 1024;
        #pragma unroll
        for (int kk = 0; kk < 64; kk += 4) {
            float4 a0 = *(const float4*)&s0[kk];
            float4 a1 = *(const float4*)&s1[kk];
            float4 a2 = *(const float4*)&s2[kk];
            float4 a3 = *(const float4*)&s3[kk];
            float2 v0 = *(const float2*)&KVt[(kk + 0) * 68 + dv0];
            float2 v1 = *(const float2*)&KVt[(kk + 1) * 68 + dv0];
            float2 v2 = *(const float2*)&KVt[(kk + 2) * 68 + dv0];
            float2 v3 = *(const float2*)&KVt[(kk + 3) * 68 + dv0];
            o00 += a0.x * v0.x; o01 += a0.x * v0.y;
            o10 += a1.x * v0.x; o11 += a1.x * v0.y;
            o20 += a2.x * v0.x; o21 += a2.x * v0.y;
            o30 += a3.x * v0.x; o31 += a3.x * v0.y;
            o00 += a0.y * v1.x; o01 += a0.y * v1.y;
            o10 += a1.y * v1.x; o11 += a1.y * v1.y;
            o20 += a2.y * v1.x; o21 += a2.y * v1.y;
            o30 += a3.y * v1.x; o31 += a3.y * v1.y;
            o00 += a0.z * v2.x; o01 += a0.z * v2.y;
            o10 += a1.z * v2.x; o11 += a1.z * v2.y;
            o20 += a2.z * v2.x; o21 += a2.z * v2.y;
            o30 += a3.z * v2.x; o31 += a3.z * v2.y;
            o00 += a0.w * v3.x; o01 += a0.w * v3.y;
            o10 += a1.w * v3.x; o11 += a1.w * v3.y;
            o20 += a2.w * v3.x; o21 += a2.w * v3.y;
            o30 += a3.w * v3.x; o31 += a3.w * v3.y;
        }
    }
    {
        size_t base = ((size_t)b * 1024 + q0 + rq * 4) * 512 + h * 64 + dv0;
        store_hl2(&g_atth[base       ], &g_attl[base       ], o00, o01);
        store_hl2(&g_atth[base +  512], &g_attl[base +  512], o10, o11);
        store_hl2(&g_atth[base + 1024], &g_attl[base + 1024], o20, o21);
        store_hl2(&g_atth[base + 1536], &g_attl[base + 1536], o30, o31);
    }
}

// ---------------- launch ----------------
extern "C" void kernel_launch(void* const* d_in, const int* in_sizes, int n_in,
                              void* d_out, int out_size)
{
    (void)in_sizes; (void)n_in; (void)out_size;
    const float* q   = (const float*)d_in[0];
    const float* k   = (const float*)d_in[1];
    const float* v   = (const float*)d_in[2];
    const int*   msk = (const int*)d_in[3];
    const float* Wq  = (const float*)d_in[4];
    const float* Wk  = (const float*)d_in[5];
    const float* Wv  = (const float*)d_in[6];
    const float* Wfc = (const float*)d_in[7];
    const float* g1  = (const float*)d_in[8];
    const float* b1  = (const float*)d_in[9];
    const float* g2  = (const float*)d_in[10];
    const float* b2  = (const float*)d_in[11];
    const float* g3  = (const float*)d_in[12];
    const float* b3  = (const float*)d_in[13];

    float* out = (float*)d_out;
    float* dyn_out  = out;                            // [16,1024,512]
    float* attn_out = out + (size_t)MROWS * 512;      // [128,1024,1024]

    const int attn_smem = (32 * 1024 + 64 * 40 + 64 * 68) * 4;    // 158720 B
    const int gemm_smem = 4 * STG;                                // 131072 B
    cudaFuncSetAttribute(attn_kernel, cudaFuncAttributeMaxDynamicSharedMemorySize, attn_smem);
    cudaFuncSetAttribute(gemm_mma_kernel, cudaFuncAttributeMaxDynamicSharedMemorySize, gemm_smem);

    ln_stats_kernel<<<dim3(2048, 3), 256>>>(q, k, v);
    convert_ln_kernel<<<dim3(2048, 3), 256>>>(q, k, v, g1, b1, g2, b2, g3, b3);
    convert_w_kernel<<<1024, 256>>>(Wq, Wk, Wv, Wfc);
    gemm_mma_kernel<<<dim3(4, 128, 3), 256, gemm_smem>>>(nullptr, 0);   // Q,K,V projections
    attn_kernel<<<dim3(32, 8, 16), 256, attn_smem>>>(msk, attn_out);
    gemm_mma_kernel<<<dim3(4, 128, 1), 256, gemm_smem>>>(dyn_out, 1);   // fc
}

// round 5
// speedup vs baseline: 1.1713x; 1.0015x over previous
#include <cuda_runtime.h>
#include <cuda_bf16.h>

#define NB 16
#define NL 1024
#define NDIN 512
#define NH 8
#define MROWS (NB*NL)   // 16384

// ---------------- scratch (device globals: no allocation allowed) ----------------
__device__ float g_mu[3][MROWS];
__device__ float g_rstd[3][MROWS];
__device__ __align__(16) float g_Q[NB*NH*NL*64];      // [b,h,l,d]  32MB
__device__ __align__(16) float g_K[NB*NH*NL*64];
__device__ __align__(16) float g_V[NB*NH*NL*64];
__device__ __align__(16) __nv_bfloat16 g_Ah[3][MROWS*512];   // LN(x) hi
__device__ __align__(16) __nv_bfloat16 g_Al[3][MROWS*512];   // LN(x) lo
__device__ __align__(16) __nv_bfloat16 g_Wh[4][512*512];     // Wq,Wk,Wv,Wfc hi
__device__ __align__(16) __nv_bfloat16 g_Wl[4][512*512];
__device__ __align__(16) __nv_bfloat16 g_atth[MROWS*512];    // attn concat out hi
__device__ __align__(16) __nv_bfloat16 g_attl[MROWS*512];

// ---------------- helpers ----------------
__device__ __forceinline__ unsigned smem_u32(const void* p) {
    unsigned a;
    asm("{ .reg .u64 t; cvta.to.shared.u64 t, %1; cvt.u32.u64 %0, t; }" : "=r"(a) : "l"(p));
    return a;
}
__device__ __forceinline__ void cp16(unsigned dst, const void* src) {
    asm volatile("cp.async.cg.shared.global [%0], [%1], 16;" :: "r"(dst), "l"(src));
}
__device__ __forceinline__ void ldm4(unsigned& r0, unsigned& r1, unsigned& r2, unsigned& r3, unsigned a) {
    asm volatile("ldmatrix.sync.aligned.m8n8.x4.shared.b16 {%0,%1,%2,%3}, [%4];"
                 : "=r"(r0), "=r"(r1), "=r"(r2), "=r"(r3) : "r"(a));
}
__device__ __forceinline__ void mma_bf16(float* d, const unsigned* a, unsigned b0, unsigned b1) {
    asm volatile(
        "mma.sync.aligned.m16n8k16.row.col.f32.bf16.bf16.f32 "
        "{%0,%1,%2,%3}, {%4,%5,%6,%7}, {%8,%9}, {%0,%1,%2,%3};"
        : "+f"(d[0]), "+f"(d[1]), "+f"(d[2]), "+f"(d[3])
        : "r"(a[0]), "r"(a[1]), "r"(a[2]), "r"(a[3]), "r"(b0), "r"(b1));
}
__device__ __forceinline__ void split_hl(float y, __nv_bfloat16& h, __nv_bfloat16& l) {
    h = __float2bfloat16(y);
    l = __float2bfloat16(y - __bfloat162float(h));
}
__device__ __forceinline__ void store_hl2(__nv_bfloat16* ph, __nv_bfloat16* pl, float a, float b) {
    __nv_bfloat162 H, L;
    split_hl(a, H.x, L.x);
    split_hl(b, H.y, L.y);
    *(__nv_bfloat162*)ph = H;
    *(__nv_bfloat162*)pl = L;
}

// ---------------- LayerNorm row statistics ----------------
__global__ __launch_bounds__(256) void ln_stats_kernel(
    const float* __restrict__ q, const float* __restrict__ k, const float* __restrict__ v)
{
    int warp = threadIdx.x >> 5, lane = threadIdx.x & 31;
    int row = blockIdx.x * 8 + warp;
    int t = blockIdx.y;
    const float* x = (t == 0 ? q : (t == 1 ? k : v)) + (size_t)row * NDIN;
    const float4* x4 = (const float4*)x;
    float s = 0.f, ss = 0.f;
    #pragma unroll
    for (int i = 0; i < 4; i++) {
        float4 a = x4[lane + 32 * i];
        s  += a.x + a.y + a.z + a.w;
        ss += a.x*a.x + a.y*a.y + a.z*a.z + a.w*a.w;
    }
    #pragma unroll
    for (int o = 16; o; o >>= 1) {
        s  += __shfl_xor_sync(0xffffffffu, s, o);
        ss += __shfl_xor_sync(0xffffffffu, ss, o);
    }
    if (lane == 0) {
        float mu = s * (1.f / 512.f);
        float var = ss * (1.f / 512.f) - mu * mu;
        g_mu[t][row] = mu;
        g_rstd[t][row] = rsqrtf(var + 1e-5f);
    }
}

// ---------------- LN apply + bf16 hi/lo split ----------------
__global__ __launch_bounds__(256) void convert_ln_kernel(
    const float* __restrict__ q, const float* __restrict__ k, const float* __restrict__ v,
    const float* __restrict__ g1, const float* __restrict__ b1,
    const float* __restrict__ g2, const float* __restrict__ b2,
    const float* __restrict__ g3, const float* __restrict__ b3)
{
    int warp = threadIdx.x >> 5, lane = threadIdx.x & 31;
    int t = blockIdx.y;
    int row = blockIdx.x * 8 + warp;
    const float* x  = (t == 0 ? q  : (t == 1 ? k  : v))  + (size_t)row * 512;
    const float* G  = (t == 0 ? g1 : (t == 1 ? g2 : g3));
    const float* Bt = (t == 0 ? b1 : (t == 1 ? b2 : b3));
    float mu = g_mu[t][row], rs = g_rstd[t][row];
    __nv_bfloat16* ph = g_Ah[t] + (size_t)row * 512;
    __nv_bfloat16* pl = g_Al[t] + (size_t)row * 512;
    #pragma unroll
    for (int i = 0; i < 4; i++) {
        int c4 = lane + 32 * i;
        float4 xv = ((const float4*)x)[c4];
        float4 gv = ((const float4*)G)[c4];
        float4 bv = ((const float4*)Bt)[c4];
        float y[4];
        y[0] = (xv.x - mu) * rs * gv.x + bv.x;
        y[1] = (xv.y - mu) * rs * gv.y + bv.y;
        y[2] = (xv.z - mu) * rs * gv.z + bv.z;
        y[3] = (xv.w - mu) * rs * gv.w + bv.w;
        __nv_bfloat16 hh[4], ll[4];
        #pragma unroll
        for (int j = 0; j < 4; j++) split_hl(y[j], hh[j], ll[j]);
        *(uint2*)(ph + c4 * 4) = *(uint2*)hh;
        *(uint2*)(pl + c4 * 4) = *(uint2*)ll;
    }
}

// ---------------- W hi/lo split ----------------
__global__ __launch_bounds__(256) void convert_w_kernel(
    const float* __restrict__ Wq, const float* __restrict__ Wk,
    const float* __restrict__ Wv, const float* __restrict__ Wfc)
{
    int idx = (blockIdx.x * 256 + threadIdx.x) * 4;
    int mat = idx >> 18;
    int off = idx & 262143;
    const float* W = (mat == 0) ? Wq : ((mat == 1) ? Wk : ((mat == 2) ? Wv : Wfc));
    float4 xv = *(const float4*)(W + off);
    float y[4] = {xv.x, xv.y, xv.z, xv.w};
    __nv_bfloat16 hh[4], ll[4];
    #pragma unroll
    for (int j = 0; j < 4; j++) split_hl(y[j], hh[j], ll[j]);
    *(uint2*)(g_Wh[mat] + off) = *(uint2*)hh;
    *(uint2*)(g_Wl[mat] + off) = *(uint2*)ll;
}

// ---------------- mma.sync GEMM: C = A @ W^T (bf16 hi/lo 3-term) ----------------
// BM=BN=128, BK=32. Stage smem: Ah 8K | Al 8K | Bh 8K | Bl 8K = 32KB, 4 stages.
// Layout per version: [kc(2)][row(128)][16 bf16 = 2 x 16B chunks], chunk swizzled
// by (row>>2)&1 so ldmatrix.x4 phases are bank-conflict-free.
#define STG 32768
#define VOFF_AL 8192
#define VOFF_BH 16384
#define VOFF_BL 24576

__device__ __forceinline__ void load_stage_mma(
    const __nv_bfloat16* __restrict__ Ah, const __nv_bfloat16* __restrict__ Al,
    const __nv_bfloat16* __restrict__ Bh, const __nv_bfloat16* __restrict__ Bl,
    int mr0, int nr0, int kb, unsigned dstb, int tid)
{
    int m = tid >> 1;
    int c = tid & 1;
    unsigned dst0 = dstb + m * 32 + ((unsigned)(c ^ ((m >> 2) & 1)) << 4);
    size_t ga = (size_t)(mr0 + m) * 512 + kb + c * 8;
    size_t gb = (size_t)(nr0 + m) * 512 + kb + c * 8;
    #pragma unroll
    for (int kc = 0; kc < 2; kc++) {
        cp16(dst0 + kc * 4096,           Ah + ga + kc * 16);
        cp16(dst0 + kc * 4096 + VOFF_AL, Al + ga + kc * 16);
        cp16(dst0 + kc * 4096 + VOFF_BH, Bh + gb + kc * 16);
        cp16(dst0 + kc * 4096 + VOFF_BL, Bl + gb + kc * 16);
    }
    asm volatile("cp.async.commit_group;");
}

__global__ __launch_bounds__(256, 1) void gemm_mma_kernel(float* __restrict__ c_fc, int mode)
{
    extern __shared__ char smem[];
    unsigned sb = smem_u32(smem);
    int tid = threadIdx.x, wid = tid >> 5, lane = tid & 31;
    int z = blockIdx.z;
    int mr0 = blockIdx.y * 128;
    int nr0 = blockIdx.x * 128;

    const __nv_bfloat16 *Ah, *Al, *Wh, *Wl;
    float* outp;
    if (mode == 0) {
        Ah = g_Ah[z]; Al = g_Al[z]; Wh = g_Wh[z]; Wl = g_Wl[z];
        outp = (z == 0) ? g_Q : ((z == 1) ? g_K : g_V);
    } else {
        Ah = g_atth; Al = g_attl; Wh = g_Wh[3]; Wl = g_Wl[3];
        outp = c_fc;
    }

    // per-thread ldmatrix address offset (row-within-16-tile + swizzled chunk)
    int rA = (lane & 7) + ((lane >> 3) & 1) * 8;
    int chv = lane >> 4;
    unsigned offT = (unsigned)(rA * 32 + ((chv ^ ((rA >> 2) & 1)) << 4));
    int wm = wid >> 2, wn = wid & 3;   // warp tile: rows wm*64, cols wn*32

    float acc[4][4][4];
    #pragma unroll
    for (int a = 0; a < 4; a++)
        #pragma unroll
        for (int b = 0; b < 4; b++)
            #pragma unroll
            for (int c = 0; c < 4; c++) acc[a][b][c] = 0.f;

    // prologue: stages 0..2
    load_stage_mma(Ah, Al, Wh, Wl, mr0, nr0, 0,  sb,           tid);
    load_stage_mma(Ah, Al, Wh, Wl, mr0, nr0, 32, sb + STG,     tid);
    load_stage_mma(Ah, Al, Wh, Wl, mr0, nr0, 64, sb + 2 * STG, tid);

    #pragma unroll 1
    for (int s = 0; s < 16; s++) {
        asm volatile("cp.async.wait_group 2;");
        __syncthreads();
        unsigned buf = sb + (unsigned)(s & 3) * STG;

        #pragma unroll
        for (int kc = 0; kc < 2; kc++) {
            unsigned abase = buf + kc * 4096;
            unsigned bbase = buf + VOFF_BH + kc * 4096;
            unsigned aH[4][4], bH[2][4];
            #pragma unroll
            for (int mt = 0; mt < 4; mt++)
                ldm4(aH[mt][0], aH[mt][1], aH[mt][2], aH[mt][3],
                     abase + (unsigned)((wm * 64 + mt * 16) * 32) + offT);
            #pragma unroll
            for (int bt = 0; bt < 2; bt++)
                ldm4(bH[bt][0], bH[bt][1], bH[bt][2], bH[bt][3],
                     bbase + (unsigned)((wn * 32 + bt * 16) * 32) + offT);
            // pass 1: Ah * Bh
            #pragma unroll
            for (int mt = 0; mt < 4; mt++)
                #pragma unroll
                for (int nt = 0; nt < 4; nt++)
                    mma_bf16(acc[mt][nt], aH[mt], bH[nt >> 1][nt & 1], bH[nt >> 1][(nt & 1) + 2]);
            // pass 2: Ah * Bl
            {
                unsigned bL[2][4];
                #pragma unroll
                for (int bt = 0; bt < 2; bt++)
                    ldm4(bL[bt][0], bL[bt][1], bL[bt][2], bL[bt][3],
                         bbase + 8192 + (unsigned)((wn * 32 + bt * 16) * 32) + offT);
                #pragma unroll
                for (int mt = 0; mt < 4; mt++)
                    #pragma unroll
                    for (int nt = 0; nt < 4; nt++)
                        mma_bf16(acc[mt][nt], aH[mt], bL[nt >> 1][nt & 1], bL[nt >> 1][(nt & 1) + 2]);
            }
            // pass 3: Al * Bh
            {
                unsigned aL[4][4];
                #pragma unroll
                for (int mt = 0; mt < 4; mt++)
                    ldm4(aL[mt][0], aL[mt][1], aL[mt][2], aL[mt][3],
                         abase + VOFF_AL + (unsigned)((wm * 64 + mt * 16) * 32) + offT);
                #pragma unroll
                for (int mt = 0; mt < 4; mt++)
                    #pragma unroll
                    for (int nt = 0; nt < 4; nt++)
                        mma_bf16(acc[mt][nt], aL[mt], bH[nt >> 1][nt & 1], bH[nt >> 1][(nt & 1) + 2]);
            }
        }

        if (s + 3 < 16)
            load_stage_mma(Ah, Al, Wh, Wl, mr0, nr0, (s + 3) * 32, sb + (unsigned)((s + 3) & 3) * STG, tid);
        else
            asm volatile("cp.async.commit_group;");
    }

    // ---- epilogue ----
    int gr = lane >> 2, gc = (lane & 3) * 2;
    #pragma unroll
    for (int mt = 0; mt < 4; mt++) {
        #pragma unroll
        for (int nt = 0; nt < 4; nt++) {
            int r0 = mr0 + wm * 64 + mt * 16 + gr;
            int n0 = nr0 + wn * 32 + nt * 8 + gc;
            if (mode == 0) {
                int h = n0 >> 6, d = n0 & 63;
                int bb = r0 >> 10, li = r0 & 1023;
                float* p0 = outp + ((size_t)(bb * 8 + h) << 16) + (size_t)li * 64 + d;
                float* p1 = outp + ((size_t)(((r0 + 8) >> 10) * 8 + h) << 16) + (size_t)((r0 + 8) & 1023) * 64 + d;
                *(float2*)p0 = make_float2(acc[mt][nt][0], acc[mt][nt][1]);
                *(float2*)p1 = make_float2(acc[mt][nt][2], acc[mt][nt][3]);
            } else {
                float* p0 = outp + (size_t)r0 * 512 + n0;
                *(float2*)p0 = make_float2(acc[mt][nt][0], acc[mt][nt][1]);
                *(float2*)(p0 + 8 * 512) = make_float2(acc[mt][nt][2], acc[mt][nt][3]);
            }
        }
    }
}

// ---------------- fused attention: scores + masked softmax + attn write + PV ----------------
__global__ __launch_bounds__(256, 1) void attn_kernel(
    const int* __restrict__ mask, float* __restrict__ attn_out)
{
    extern __shared__ float sm[];
    float* Ssc = sm;                    // [32][1024]
    float* Qt  = sm + 32 * 1024;        // [64][40]
    float* KVt = Qt + 64 * 40;          // [64][68]

    int tid = threadIdx.x;
    int q0 = blockIdx.x * 32;
    int h = blockIdx.y, b = blockIdx.z;
    size_t bh = (size_t)(b * NH + h);
    const float* Qg = g_Q + (bh << 16) + (size_t)q0 * 64;
    const float* Kg = g_K + (bh << 16);
    const float* Vg = g_V + (bh << 16);

    {
        int r = tid >> 3;
        int dq = (tid & 7) * 8;
        float4 v0 = *(const float4*)&Qg[r * 64 + dq];
        float4 v1 = *(const float4*)&Qg[r * 64 + dq + 4];
        Qt[(dq + 0) * 40 + r] = v0.x; Qt[(dq + 1) * 40 + r] = v0.y;
        Qt[(dq + 2) * 40 + r] = v0.z; Qt[(dq + 3) * 40 + r] = v0.w;
        Qt[(dq + 4) * 40 + r] = v1.x; Qt[(dq + 5) * 40 + r] = v1.y;
        Qt[(dq + 6) * 40 + r] = v1.z; Qt[(dq + 7) * 40 + r] = v1.w;
    }

    int cp = tid & 31, rq = tid >> 5;
    int c0 = cp * 2;

    for (int kt = 0; kt < 16; kt++) {
        __syncthreads();
        {
            int c = tid >> 2, f = tid & 3;
            const float* src = &Kg[(kt * 64 + c) * 64];
            #pragma unroll
            for (int jj = 0; jj < 4; jj++) {
                int d0 = f * 16 + jj * 4;
                float4 kv = *(const float4*)&src[d0];
                KVt[(d0 + 0) * 68 + c] = kv.x;
                KVt[(d0 + 1) * 68 + c] = kv.y;
                KVt[(d0 + 2) * 68 + c] = kv.z;
                KVt[(d0 + 3) * 68 + c] = kv.w;
            }
        }
        __syncthreads();
        float a00 = 0, a01 = 0, a10 = 0, a11 = 0, a20 = 0, a21 = 0, a30 = 0, a31 = 0;
        #pragma unroll
        for (int d = 0; d < 64; d++) {
            float2 kv = *(const float2*)&KVt[d * 68 + c0];
            float4 qv = *(const float4*)&Qt[d * 40 + rq * 4];
            a00 += qv.x * kv.x; a01 += qv.x * kv.y;
            a10 += qv.y * kv.x; a11 += qv.y * kv.y;
            a20 += qv.z * kv.x; a21 += qv.z * kv.y;
            a30 += qv.w * kv.x; a31 += qv.w * kv.y;
        }
        const float sc = 0.125f;
        int col = kt * 64 + c0;
        *(float2*)&Ssc[(rq * 4 + 0) * 1024 + col] = make_float2(a00 * sc, a01 * sc);
        *(float2*)&Ssc[(rq * 4 + 1) * 1024 + col] = make_float2(a10 * sc, a11 * sc);
        *(float2*)&Ssc[(rq * 4 + 2) * 1024 + col] = make_float2(a20 * sc, a21 * sc);
        *(float2*)&Ssc[(rq * 4 + 3) * 1024 + col] = make_float2(a30 * sc, a31 * sc);
    }
    __syncthreads();

    {
        int warp = tid >> 5, lane = tid & 31;
        for (int rr = 0; rr < 4; rr++) {
            int r = warp * 4 + rr;
            int qg = q0 + r;
            const int* mrow = mask + ((size_t)b * 1024 + qg) * 1024;
            float* srow = &Ssc[r * 1024];
            float mx = 0.f; int cnt = 0;
            for (int kk = lane; kk < 1024; kk += 32) {
                float s = srow[kk];
                int mk = mrow[kk];
                bool allowed = (kk != qg) && (mk == 0);
                float tt = allowed ? s : 0.f;
                srow[kk] = tt;
                cnt += allowed ? 0 : 1;
                mx = fmaxf(mx, tt);
            }
            #pragma unroll
            for (int o = 16; o; o >>= 1) {
                mx = fmaxf(mx, __shfl_xor_sync(0xffffffffu, mx, o));
                cnt += __shfl_xor_sync(0xffffffffu, cnt, o);
            }
            float sum = 0.f;
            for (int kk = lane; kk < 1024; kk += 32) {
                float tt = srow[kk];
                float e = (tt != 0.f) ? __expf(tt - mx) : 0.f;
                srow[kk] = e;
                sum += e;
            }
            #pragma unroll
            for (int o = 16; o; o >>= 1) sum += __shfl_xor_sync(0xffffffffu, sum, o);
            float Z = sum + (float)cnt * __expf(-mx);
            float inv = 1.f / (sum + 1e-13f * Z);
            float* orow = attn_out + (((size_t)h * NB + b) * 1024 + qg) * 1024;
            for (int kk = lane; kk < 1024; kk += 32) {
                float a = srow[kk] * inv;
                srow[kk] = a;
                orow[kk] = a;
            }
        }
    }

    int dv0 = c0;
    float o00 = 0, o01 = 0, o10 = 0, o11 = 0, o20 = 0, o21 = 0, o30 = 0, o31 = 0;
    for (int kt = 0; kt < 16; kt++) {
        __syncthreads();
        {
            int kk = tid >> 2, f = tid & 3;
            const float* src = &Vg[(kt * 64 + kk) * 64];
            #pragma unroll
            for (int jj = 0; jj < 4; jj++) {
                int d0 = f * 16 + jj * 4;
                *(float4*)&KVt[kk * 68 + d0] = *(const float4*)&src[d0];
            }
        }
        __syncthreads();
        const float* s0 = &Ssc[(rq * 4 + 0) * 1024 + kt * 64];
        const float* s1 = s0 + 1024;
        const float* s2 = s1 + 1024;
        const float* s3 = s2 + 1024;
        #pragma unroll
        for (int kk = 0; kk < 64; kk += 4) {
            float4 a0 = *(const float4*)&s0[kk];
            float4 a1 = *(const float4*)&s1[kk];
            float4 a2 = *(const float4*)&s2[kk];
            float4 a3 = *(const float4*)&s3[kk];
            float2 v0 = *(const float2*)&KVt[(kk + 0) * 68 + dv0];
            float2 v1 = *(const float2*)&KVt[(kk + 1) * 68 + dv0];
            float2 v2 = *(const float2*)&KVt[(kk + 2) * 68 + dv0];
            float2 v3 = *(const float2*)&KVt[(kk + 3) * 68 + dv0];
            o00 += a0.x * v0.x; o01 += a0.x * v0.y;
            o10 += a1.x * v0.x; o11 += a1.x * v0.y;
            o20 += a2.x * v0.x; o21 += a2.x * v0.y;
            o30 += a3.x * v0.x; o31 += a3.x * v0.y;
            o00 += a0.y * v1.x; o01 += a0.y * v1.y;
            o10 += a1.y * v1.x; o11 += a1.y * v1.y;
            o20 += a2.y * v1.x; o21 += a2.y * v1.y;
            o30 += a3.y * v1.x; o31 += a3.y * v1.y;
            o00 += a0.z * v2.x; o01 += a0.z * v2.y;
            o10 += a1.z * v2.x; o11 += a1.z * v2.y;
            o20 += a2.z * v2.x; o21 += a2.z * v2.y;
            o30 += a3.z * v2.x; o31 += a3.z * v2.y;
            o00 += a0.w * v3.x; o01 += a0.w * v3.y;
            o10 += a1.w * v3.x; o11 += a1.w * v3.y;
            o20 += a2.w * v3.x; o21 += a2.w * v3.y;
            o30 += a3.w * v3.x; o31 += a3.w * v3.y;
        }
    }
    {
        size_t base = ((size_t)b * 1024 + q0 + rq * 4) * 512 + h * 64 + dv0;
        store_hl2(&g_atth[base       ], &g_attl[base       ], o00, o01);
        store_hl2(&g_atth[base +  512], &g_attl[base +  512], o10, o11);
        store_hl2(&g_atth[base + 1024], &g_attl[base + 1024], o20, o21);
        store_hl2(&g_atth[base + 1536], &g_attl[base + 1536], o30, o31);
    }
}

// ---------------- launch ----------------
extern "C" void kernel_launch(void* const* d_in, const int* in_sizes, int n_in,
                              void* d_out, int out_size)
{
    (void)in_sizes; (void)n_in; (void)out_size;
    const float* q   = (const float*)d_in[0];
    const float* k   = (const float*)d_in[1];
    const float* v   = (const float*)d_in[2];
    const int*   msk = (const int*)d_in[3];
    const float* Wq  = (const float*)d_in[4];
    const float* Wk  = (const float*)d_in[5];
    const float* Wv  = (const float*)d_in[6];
    const float* Wfc = (const float*)d_in[7];
    const float* g1  = (const float*)d_in[8];
    const float* b1  = (const float*)d_in[9];
    const float* g2  = (const float*)d_in[10];
    const float* b2  = (const float*)d_in[11];
    const float* g3  = (const float*)d_in[12];
    const float* b3  = (const float*)d_in[13];

    float* out = (float*)d_out;
    float* dyn_out  = out;                            // [16,1024,512]
    float* attn_out = out + (size_t)MROWS * 512;      // [128,1024,1024]

    const int attn_smem = (32 * 1024 + 64 * 40 + 64 * 68) * 4;    // 158720 B
    const int gemm_smem = 4 * STG;                                // 131072 B
    cudaFuncSetAttribute(attn_kernel, cudaFuncAttributeMaxDynamicSharedMemorySize, attn_smem);
    cudaFuncSetAttribute(gemm_mma_kernel, cudaFuncAttributeMaxDynamicSharedMemorySize, gemm_smem);

    ln_stats_kernel<<<dim3(2048, 3), 256>>>(q, k, v);
    convert_ln_kernel<<<dim3(2048, 3), 256>>>(q, k, v, g1, b1, g2, b2, g3, b3);
    convert_w_kernel<<<1024, 256>>>(Wq, Wk, Wv, Wfc);
    gemm_mma_kernel<<<dim3(4, 128, 3), 256, gemm_smem>>>(nullptr, 0);   // Q,K,V projections
    attn_kernel<<<dim3(32, 8, 16), 256, attn_smem>>>(msk, attn_out);
    gemm_mma_kernel<<<dim3(4, 128, 1), 256, gemm_smem>>>(dyn_out, 1);   // fc
}

// round 6
// speedup vs baseline: 1.9276x; 1.6457x over previous
#include <cuda_runtime.h>
#include <cuda_bf16.h>

#define NB 16
#define NL 1024
#define NH 8
#define MROWS (NB*NL)

// ---------------- scratch ----------------
__device__ float g_mu[3][MROWS];
__device__ float g_rstd[3][MROWS];
__device__ __align__(16) __nv_bfloat16 g_Qh[NB*NH*NL*64];
__device__ __align__(16) __nv_bfloat16 g_Ql[NB*NH*NL*64];
__device__ __align__(16) __nv_bfloat16 g_Kh[NB*NH*NL*64];
__device__ __align__(16) __nv_bfloat16 g_Kl[NB*NH*NL*64];
__device__ __align__(16) __nv_bfloat16 g_Vh[NB*NH*NL*64];
__device__ __align__(16) __nv_bfloat16 g_Vl[NB*NH*NL*64];
__device__ __align__(16) __nv_bfloat16 g_Ah[3][MROWS*512];
__device__ __align__(16) __nv_bfloat16 g_Al[3][MROWS*512];
__device__ __align__(16) __nv_bfloat16 g_Wh[4][512*512];
__device__ __align__(16) __nv_bfloat16 g_Wl[4][512*512];
__device__ __align__(16) __nv_bfloat16 g_atth[MROWS*512];
__device__ __align__(16) __nv_bfloat16 g_attl[MROWS*512];

// ---------------- helpers ----------------
__device__ __forceinline__ unsigned smem_u32(const void* p) {
    unsigned a;
    asm("{ .reg .u64 t; cvta.to.shared.u64 t, %1; cvt.u32.u64 %0, t; }" : "=r"(a) : "l"(p));
    return a;
}
__device__ __forceinline__ void cp16(unsigned dst, const void* src) {
    asm volatile("cp.async.cg.shared.global [%0], [%1], 16;" :: "r"(dst), "l"(src));
}
__device__ __forceinline__ void ldm4(unsigned& r0, unsigned& r1, unsigned& r2, unsigned& r3, unsigned a) {
    asm volatile("ldmatrix.sync.aligned.m8n8.x4.shared.b16 {%0,%1,%2,%3}, [%4];"
                 : "=r"(r0), "=r"(r1), "=r"(r2), "=r"(r3) : "r"(a));
}
__device__ __forceinline__ void ldm4t(unsigned& r0, unsigned& r1, unsigned& r2, unsigned& r3, unsigned a) {
    asm volatile("ldmatrix.sync.aligned.m8n8.x4.trans.shared.b16 {%0,%1,%2,%3}, [%4];"
                 : "=r"(r0), "=r"(r1), "=r"(r2), "=r"(r3) : "r"(a));
}
__device__ __forceinline__ void mma_bf16(float* d, const unsigned* a, unsigned b0, unsigned b1) {
    asm volatile(
        "mma.sync.aligned.m16n8k16.row.col.f32.bf16.bf16.f32 "
        "{%0,%1,%2,%3}, {%4,%5,%6,%7}, {%8,%9}, {%0,%1,%2,%3};"
        : "+f"(d[0]), "+f"(d[1]), "+f"(d[2]), "+f"(d[3])
        : "r"(a[0]), "r"(a[1]), "r"(a[2]), "r"(a[3]), "r"(b0), "r"(b1));
}
__device__ __forceinline__ void split_hl(float y, __nv_bfloat16& h, __nv_bfloat16& l) {
    h = __float2bfloat16(y);
    l = __float2bfloat16(y - __bfloat162float(h));
}
__device__ __forceinline__ void store_hl2(__nv_bfloat16* ph, __nv_bfloat16* pl, float a, float b) {
    __nv_bfloat162 H, L;
    split_hl(a, H.x, L.x);
    split_hl(b, H.y, L.y);
    *(__nv_bfloat162*)ph = H;
    *(__nv_bfloat162*)pl = L;
}
__device__ __forceinline__ unsigned pack_hi(float a, float b) {
    __nv_bfloat162 H; H.x = __float2bfloat16(a); H.y = __float2bfloat16(b);
    return *(unsigned*)&H;
}
__device__ __forceinline__ unsigned pack_lo(float a, float b) {
    __nv_bfloat16 ha = __float2bfloat16(a), hb = __float2bfloat16(b);
    __nv_bfloat162 L;
    L.x = __float2bfloat16(a - __bfloat162float(ha));
    L.y = __float2bfloat16(b - __bfloat162float(hb));
    return *(unsigned*)&L;
}

// ---------------- LN stats ----------------
__global__ __launch_bounds__(256) void ln_stats_kernel(
    const float* __restrict__ q, const float* __restrict__ k, const float* __restrict__ v)
{
    int warp = threadIdx.x >> 5, lane = threadIdx.x & 31;
    int row = blockIdx.x * 8 + warp;
    int t = blockIdx.y;
    const float4* x4 = (const float4*)((t == 0 ? q : (t == 1 ? k : v)) + (size_t)row * 512);
    float s = 0.f, ss = 0.f;
    #pragma unroll
    for (int i = 0; i < 4; i++) {
        float4 a = x4[lane + 32 * i];
        s  += a.x + a.y + a.z + a.w;
        ss += a.x*a.x + a.y*a.y + a.z*a.z + a.w*a.w;
    }
    #pragma unroll
    for (int o = 16; o; o >>= 1) {
        s  += __shfl_xor_sync(0xffffffffu, s, o);
        ss += __shfl_xor_sync(0xffffffffu, ss, o);
    }
    if (lane == 0) {
        float mu = s * (1.f / 512.f);
        float var = ss * (1.f / 512.f) - mu * mu;
        g_mu[t][row] = mu;
        g_rstd[t][row] = rsqrtf(var + 1e-5f);
    }
}

// ---------------- LN apply + split ----------------
__global__ __launch_bounds__(256) void convert_ln_kernel(
    const float* __restrict__ q, const float* __restrict__ k, const float* __restrict__ v,
    const float* __restrict__ g1, const float* __restrict__ b1,
    const float* __restrict__ g2, const float* __restrict__ b2,
    const float* __restrict__ g3, const float* __restrict__ b3)
{
    int warp = threadIdx.x >> 5, lane = threadIdx.x & 31;
    int t = blockIdx.y;
    int row = blockIdx.x * 8 + warp;
    const float* x  = (t == 0 ? q  : (t == 1 ? k  : v))  + (size_t)row * 512;
    const float* G  = (t == 0 ? g1 : (t == 1 ? g2 : g3));
    const float* Bt = (t == 0 ? b1 : (t == 1 ? b2 : b3));
    float mu = g_mu[t][row], rs = g_rstd[t][row];
    __nv_bfloat16* ph = g_Ah[t] + (size_t)row * 512;
    __nv_bfloat16* pl = g_Al[t] + (size_t)row * 512;
    #pragma unroll
    for (int i = 0; i < 4; i++) {
        int c4 = lane + 32 * i;
        float4 xv = ((const float4*)x)[c4];
        float4 gv = ((const float4*)G)[c4];
        float4 bv = ((const float4*)Bt)[c4];
        float y[4];
        y[0] = (xv.x - mu) * rs * gv.x + bv.x;
        y[1] = (xv.y - mu) * rs * gv.y + bv.y;
        y[2] = (xv.z - mu) * rs * gv.z + bv.z;
        y[3] = (xv.w - mu) * rs * gv.w + bv.w;
        __nv_bfloat16 hh[4], ll[4];
        #pragma unroll
        for (int j = 0; j < 4; j++) split_hl(y[j], hh[j], ll[j]);
        *(uint2*)(ph + c4 * 4) = *(uint2*)hh;
        *(uint2*)(pl + c4 * 4) = *(uint2*)ll;
    }
}

__global__ __launch_bounds__(256) void convert_w_kernel(
    const float* __restrict__ Wq, const float* __restrict__ Wk,
    const float* __restrict__ Wv, const float* __restrict__ Wfc)
{
    int idx = (blockIdx.x * 256 + threadIdx.x) * 4;
    int mat = idx >> 18;
    int off = idx & 262143;
    const float* W = (mat == 0) ? Wq : ((mat == 1) ? Wk : ((mat == 2) ? Wv : Wfc));
    float4 xv = *(const float4*)(W + off);
    float y[4] = {xv.x, xv.y, xv.z, xv.w};
    __nv_bfloat16 hh[4], ll[4];
    #pragma unroll
    for (int j = 0; j < 4; j++) split_hl(y[j], hh[j], ll[j]);
    *(uint2*)(g_Wh[mat] + off) = *(uint2*)hh;
    *(uint2*)(g_Wl[mat] + off) = *(uint2*)ll;
}

// ---------------- mma.sync GEMM ----------------
#define STG 32768
#define VOFF_AL 8192
#define VOFF_BH 16384
#define VOFF_BL 24576

__device__ __forceinline__ void load_stage_mma(
    const __nv_bfloat16* __restrict__ Ah, const __nv_bfloat16* __restrict__ Al,
    const __nv_bfloat16* __restrict__ Bh, const __nv_bfloat16* __restrict__ Bl,
    int mr0, int nr0, int kb, unsigned dstb, int tid)
{
    int m = tid >> 1;
    int c = tid & 1;
    unsigned dst0 = dstb + m * 32 + ((unsigned)(c ^ ((m >> 2) & 1)) << 4);
    size_t ga = (size_t)(mr0 + m) * 512 + kb + c * 8;
    size_t gb = (size_t)(nr0 + m) * 512 + kb + c * 8;
    #pragma unroll
    for (int kc = 0; kc < 2; kc++) {
        cp16(dst0 + kc * 4096,           Ah + ga + kc * 16);
        cp16(dst0 + kc * 4096 + VOFF_AL, Al + ga + kc * 16);
        cp16(dst0 + kc * 4096 + VOFF_BH, Bh + gb + kc * 16);
        cp16(dst0 + kc * 4096 + VOFF_BL, Bl + gb + kc * 16);
    }
    asm volatile("cp.async.commit_group;");
}

__global__ __launch_bounds__(256, 1) void gemm_mma_kernel(float* __restrict__ c_fc, int mode)
{
    extern __shared__ char smem[];
    unsigned sb = smem_u32(smem);
    int tid = threadIdx.x, wid = tid >> 5, lane = tid & 31;
    int z = blockIdx.z;
    int mr0 = blockIdx.y * 128;
    int nr0 = blockIdx.x * 128;

    const __nv_bfloat16 *Ah, *Al, *Wh, *Wl;
    __nv_bfloat16 *oh = 0, *ol = 0;
    if (mode == 0) {
        Ah = g_Ah[z]; Al = g_Al[z]; Wh = g_Wh[z]; Wl = g_Wl[z];
        oh = (z == 0) ? g_Qh : ((z == 1) ? g_Kh : g_Vh);
        ol = (z == 0) ? g_Ql : ((z == 1) ? g_Kl : g_Vl);
    } else {
        Ah = g_atth; Al = g_attl; Wh = g_Wh[3]; Wl = g_Wl[3];
    }

    int rA = lane & 15, chv = lane >> 4;
    unsigned offT = (unsigned)(rA * 32 + ((chv ^ ((rA >> 2) & 1)) << 4));
    int wm = wid >> 2, wn = wid & 3;

    float acc[4][4][4];
    #pragma unroll
    for (int a = 0; a < 4; a++)
        #pragma unroll
        for (int b = 0; b < 4; b++)
            #pragma unroll
            for (int c = 0; c < 4; c++) acc[a][b][c] = 0.f;

    load_stage_mma(Ah, Al, Wh, Wl, mr0, nr0, 0,  sb,           tid);
    load_stage_mma(Ah, Al, Wh, Wl, mr0, nr0, 32, sb + STG,     tid);
    load_stage_mma(Ah, Al, Wh, Wl, mr0, nr0, 64, sb + 2 * STG, tid);

    #pragma unroll 1
    for (int s = 0; s < 16; s++) {
        asm volatile("cp.async.wait_group 2;");
        __syncthreads();
        unsigned buf = sb + (unsigned)(s & 3) * STG;

        #pragma unroll
        for (int kc = 0; kc < 2; kc++) {
            unsigned abase = buf + kc * 4096;
            unsigned bbase = buf + VOFF_BH + kc * 4096;
            unsigned aH[4][4], bH[2][4];
            #pragma unroll
            for (int mt = 0; mt < 4; mt++)
                ldm4(aH[mt][0], aH[mt][1], aH[mt][2], aH[mt][3],
                     abase + (unsigned)((wm * 64 + mt * 16) * 32) + offT);
            #pragma unroll
            for (int bt = 0; bt < 2; bt++)
                ldm4(bH[bt][0], bH[bt][1], bH[bt][2], bH[bt][3],
                     bbase + (unsigned)((wn * 32 + bt * 16) * 32) + offT);
            #pragma unroll
            for (int mt = 0; mt < 4; mt++)
                #pragma unroll
                for (int nt = 0; nt < 4; nt++)
                    mma_bf16(acc[mt][nt], aH[mt], bH[nt >> 1][nt & 1], bH[nt >> 1][(nt & 1) + 2]);
            {
                unsigned bL[2][4];
                #pragma unroll
                for (int bt = 0; bt < 2; bt++)
                    ldm4(bL[bt][0], bL[bt][1], bL[bt][2], bL[bt][3],
                         bbase + 8192 + (unsigned)((wn * 32 + bt * 16) * 32) + offT);
                #pragma unroll
                for (int mt = 0; mt < 4; mt++)
                    #pragma unroll
                    for (int nt = 0; nt < 4; nt++)
                        mma_bf16(acc[mt][nt], aH[mt], bL[nt >> 1][nt & 1], bL[nt >> 1][(nt & 1) + 2]);
            }
            {
                unsigned aL[4][4];
                #pragma unroll
                for (int mt = 0; mt < 4; mt++)
                    ldm4(aL[mt][0], aL[mt][1], aL[mt][2], aL[mt][3],
                         abase + VOFF_AL + (unsigned)((wm * 64 + mt * 16) * 32) + offT);
                #pragma unroll
                for (int mt = 0; mt < 4; mt++)
                    #pragma unroll
                    for (int nt = 0; nt < 4; nt++)
                        mma_bf16(acc[mt][nt], aL[mt], bH[nt >> 1][nt & 1], bH[nt >> 1][(nt & 1) + 2]);
            }
        }

        if (s + 3 < 16)
            load_stage_mma(Ah, Al, Wh, Wl, mr0, nr0, (s + 3) * 32, sb + (unsigned)((s + 3) & 3) * STG, tid);
        else
            asm volatile("cp.async.commit_group;");
    }

    int gr = lane >> 2, gc = (lane & 3) * 2;
    #pragma unroll
    for (int mt = 0; mt < 4; mt++) {
        #pragma unroll
        for (int nt = 0; nt < 4; nt++) {
            int r0 = mr0 + wm * 64 + mt * 16 + gr;
            int n0 = nr0 + wn * 32 + nt * 8 + gc;
            if (mode == 0) {
                int h = n0 >> 6, d = n0 & 63;
                int r1 = r0 + 8;
                size_t p0 = ((size_t)((r0 >> 10) * 8 + h) << 16) + (size_t)(r0 & 1023) * 64 + d;
                size_t p1 = ((size_t)((r1 >> 10) * 8 + h) << 16) + (size_t)(r1 & 1023) * 64 + d;
                store_hl2(oh + p0, ol + p0, acc[mt][nt][0], acc[mt][nt][1]);
                store_hl2(oh + p1, ol + p1, acc[mt][nt][2], acc[mt][nt][3]);
            } else {
                float* p0 = c_fc + (size_t)r0 * 512 + n0;
                *(float2*)p0 = make_float2(acc[mt][nt][0], acc[mt][nt][1]);
                *(float2*)(p0 + 8 * 512) = make_float2(acc[mt][nt][2], acc[mt][nt][3]);
            }
        }
    }
}

// ---------------- tensor-core fused attention ----------------
// smem: [0,128K) S fp32 / P bf16 (in place); [128K,192K) K/V dbl buf; [192K,200K) Q / red
#define AKB 131072u
#define AQB 196608u

__device__ __forceinline__ void load_kt(unsigned buf, const __nv_bfloat16* Kh,
                                        const __nv_bfloat16* Kl, int it, int tid)
{
    #pragma unroll
    for (int i = 0; i < 8; i++) {
        int idx = i * 256 + tid;
        int ver = idx >> 10, g = idx & 1023;
        int row = g >> 3, cc = g & 7;
        int kc = cc >> 1, ch = cc & 1;
        unsigned dst = buf + ver * 16384 + kc * 4096 + row * 32
                     + ((unsigned)(ch ^ ((row >> 2) & 1)) << 4);
        cp16(dst, (ver ? Kl : Kh) + (size_t)(it * 128 + row) * 64 + cc * 8);
    }
    asm volatile("cp.async.commit_group;");
}
__device__ __forceinline__ void load_vt(unsigned buf, const __nv_bfloat16* Vh,
                                        const __nv_bfloat16* Vl, int it, int tid)
{
    #pragma unroll
    for (int i = 0; i < 8; i++) {
        int idx = i * 256 + tid;
        int ver = idx >> 10, g = idx & 1023;
        int row = g >> 3, cc = g & 7;
        unsigned dst = buf + ver * 16384 + row * 128 + ((unsigned)(cc ^ (row & 7)) << 4);
        cp16(dst, (ver ? Vl : Vh) + (size_t)(it * 128 + row) * 64 + cc * 8);
    }
    asm volatile("cp.async.commit_group;");
}

__global__ __launch_bounds__(256, 1) void attn_mma_kernel(
    const int* __restrict__ mask, float* __restrict__ attn_out)
{
    extern __shared__ char smc[];
    unsigned sb = smem_u32(smc);
    float* Ssc = (float*)smc;
    int tid = threadIdx.x, wid = tid >> 5, lane = tid & 31;
    int rA = lane & 15, chv = lane >> 4;
    int gr = lane >> 2, gc = (lane & 3) * 2;
    int q0 = blockIdx.x * 32;
    int bh = blockIdx.y;
    int b = bh >> 3, h = bh & 7;
    const __nv_bfloat16* Qhp = g_Qh + ((size_t)bh << 16) + (size_t)q0 * 64;
    const __nv_bfloat16* Qlp = g_Ql + ((size_t)bh << 16) + (size_t)q0 * 64;
    const __nv_bfloat16* Khp = g_Kh + ((size_t)bh << 16);
    const __nv_bfloat16* Klp = g_Kl + ((size_t)bh << 16);
    const __nv_bfloat16* Vhp = g_Vh + ((size_t)bh << 16);
    const __nv_bfloat16* Vlp = g_Vl + ((size_t)bh << 16);

    // Q tile loads (ride in K0's commit group)
    #pragma unroll
    for (int i = 0; i < 2; i++) {
        int idx = i * 256 + tid;
        int ver = idx >> 8, rest = idx & 255;
        int row = rest >> 3, cc = rest & 7;
        int kc = cc >> 1, ch = cc & 1;
        unsigned dst = sb + AQB + ver * 4096 + kc * 1024 + row * 32
                     + ((unsigned)(ch ^ ((row >> 2) & 1)) << 4);
        cp16(dst, (ver ? Qlp : Qhp) + row * 64 + cc * 8);
    }
    load_kt(sb + AKB, Khp, Klp, 0, tid);
    load_kt(sb + AKB + 32768, Khp, Klp, 1, tid);

    // ---- pass 1: S = Q K^T / 8 ----
    unsigned qf[2][4][2][4];
    int n0 = wid * 16;
    unsigned offAq[2];
    #pragma unroll
    for (int mt = 0; mt < 2; mt++) {
        int r = mt * 16 + rA;
        offAq[mt] = r * 32 + ((unsigned)(chv ^ ((r >> 2) & 1)) << 4);
    }
    int rB = n0 + rA;
    unsigned offB = rB * 32 + ((unsigned)(chv ^ ((rB >> 2) & 1)) << 4);

    #pragma unroll 1
    for (int it = 0; it < 8; it++) {
        asm volatile("cp.async.wait_group 1;" ::: "memory");
        __syncthreads();
        unsigned buf = sb + AKB + (unsigned)(it & 1) * 32768;
        if (it == 0) {
            #pragma unroll
            for (int v = 0; v < 2; v++)
                #pragma unroll
                for (int kc = 0; kc < 4; kc++)
                    #pragma unroll
                    for (int mt = 0; mt < 2; mt++)
                        ldm4(qf[v][kc][mt][0], qf[v][kc][mt][1], qf[v][kc][mt][2], qf[v][kc][mt][3],
                             sb + AQB + v * 4096 + kc * 1024 + offAq[mt]);
        }
        float acc[2][2][4];
        #pragma unroll
        for (int a = 0; a < 2; a++)
            #pragma unroll
            for (int c = 0; c < 2; c++)
                #pragma unroll
                for (int e = 0; e < 4; e++) acc[a][c][e] = 0.f;
        #pragma unroll
        for (int kc = 0; kc < 4; kc++) {
            unsigned bh4[4], bl4[4];
            ldm4(bh4[0], bh4[1], bh4[2], bh4[3], buf + kc * 4096 + offB);
            ldm4(bl4[0], bl4[1], bl4[2], bl4[3], buf + 16384 + kc * 4096 + offB);
            #pragma unroll
            for (int mt = 0; mt < 2; mt++)
                #pragma unroll
                for (int nt = 0; nt < 2; nt++) {
                    mma_bf16(acc[mt][nt], qf[0][kc][mt], bh4[nt], bh4[nt + 2]);
                    mma_bf16(acc[mt][nt], qf[0][kc][mt], bl4[nt], bl4[nt + 2]);
                    mma_bf16(acc[mt][nt], qf[1][kc][mt], bh4[nt], bh4[nt + 2]);
                }
        }
        #pragma unroll
        for (int mt = 0; mt < 2; mt++)
            #pragma unroll
            for (int nt = 0; nt < 2; nt++) {
                int r = mt * 16 + gr;
                int c = it * 128 + n0 + nt * 8 + gc;
                unsigned pc0 = (unsigned)c ^ ((unsigned)(r & 7) << 2);
                unsigned pc1 = (unsigned)c ^ ((unsigned)((r + 8) & 7) << 2);
                *(float2*)&Ssc[r * 1024 + pc0] =
                    make_float2(acc[mt][nt][0] * 0.125f, acc[mt][nt][1] * 0.125f);
                *(float2*)&Ssc[(r + 8) * 1024 + pc1] =
                    make_float2(acc[mt][nt][2] * 0.125f, acc[mt][nt][3] * 0.125f);
            }
        __syncthreads();
        if (it + 2 < 8) load_kt(buf, Khp, Klp, it + 2, tid);
        else asm volatile("cp.async.commit_group;");
    }

    // V tiles 0,1 prefetch (overlaps softmax)
    load_vt(sb + AKB, Vhp, Vlp, 0, tid);
    load_vt(sb + AKB + 32768, Vhp, Vlp, 1, tid);

    // ---- masked softmax (exact reference algebra) + attn write ----
    #pragma unroll 1
    for (int rr = 0; rr < 4; rr++) {
        int r = wid * 4 + rr;
        int qg = q0 + r;
        unsigned xr = (unsigned)(r & 7) << 2;
        const int* mrow = mask + ((size_t)b * 1024 + qg) * 1024;
        float* srow = &Ssc[r * 1024];
        float mx = 0.f; int cnt = 0;
        for (int kk = lane; kk < 1024; kk += 32) {
            float s = srow[kk ^ xr];
            int mk = mrow[kk];
            bool allowed = (kk != qg) && (mk == 0);
            float tt = allowed ? s : 0.f;
            srow[kk ^ xr] = tt;
            cnt += allowed ? 0 : 1;
            mx = fmaxf(mx, tt);
        }
        #pragma unroll
        for (int o = 16; o; o >>= 1) {
            mx = fmaxf(mx, __shfl_xor_sync(0xffffffffu, mx, o));
            cnt += __shfl_xor_sync(0xffffffffu, cnt, o);
        }
        float sum = 0.f;
        for (int kk = lane; kk < 1024; kk += 32) {
            float tt = srow[kk ^ xr];
            float e = (tt != 0.f) ? __expf(tt - mx) : 0.f;
            srow[kk ^ xr] = e;
            sum += e;
        }
        #pragma unroll
        for (int o = 16; o; o >>= 1) sum += __shfl_xor_sync(0xffffffffu, sum, o);
        float Z = sum + (float)cnt * __expf(-mx);
        float inv = 1.f / (sum + 1e-13f * Z);
        float* orow = attn_out + (((size_t)h * NB + b) * 1024 + qg) * 1024;
        for (int kk = lane; kk < 1024; kk += 32) {
            float a = srow[kk ^ xr] * inv;
            srow[kk ^ xr] = a;
            orow[kk] = a;
        }
    }
    __syncthreads();

    // ---- in-place S(fp32) -> P(bf16 hi/lo) ----
    #pragma unroll 1
    for (int j = 0; j < 16; j++) {
        int r = 2 * j + (tid >> 7);
        int kk0 = (tid & 127) * 8;
        unsigned xr = (unsigned)(r & 7) << 2;
        float4 A = *(float4*)&Ssc[r * 1024 + ((unsigned)kk0 ^ xr)];
        float4 Bv = *(float4*)&Ssc[r * 1024 + ((unsigned)(kk0 + 4) ^ xr)];
        __syncthreads();
        unsigned slot = (unsigned)((kk0 >> 3) ^ (r & 7));
        uint4 hv, lv;
        hv.x = pack_hi(A.x, A.y);   lv.x = pack_lo(A.x, A.y);
        hv.y = pack_hi(A.z, A.w);   lv.y = pack_lo(A.z, A.w);
        hv.z = pack_hi(Bv.x, Bv.y); lv.z = pack_lo(Bv.x, Bv.y);
        hv.w = pack_hi(Bv.z, Bv.w); lv.w = pack_lo(Bv.z, Bv.w);
        *(uint4*)(smc + (size_t)r * 4096 + (slot << 4)) = hv;
        *(uint4*)(smc + (size_t)r * 4096 + (slot << 4) + 2048) = lv;
        __syncthreads();
    }

    // ---- pass 2: out = P V ----
    float pacc[2][2][4];
    #pragma unroll
    for (int a = 0; a < 2; a++)
        #pragma unroll
        for (int c = 0; c < 2; c++)
            #pragma unroll
            for (int e = 0; e < 4; e++) pacc[a][c][e] = 0.f;
    int wk = wid >> 2, wn = wid & 3;

    #pragma unroll 1
    for (int kt = 0; kt < 8; kt++) {
        asm volatile("cp.async.wait_group 1;" ::: "memory");
        __syncthreads();
        unsigned buf = sb + AKB + (unsigned)(kt & 1) * 32768;
        #pragma unroll
        for (int i = 0; i < 4; i++) {
            int s8 = wk * 4 + i;
            int kseg = kt * 8 + s8;
            unsigned pf[2][2][4];
            #pragma unroll
            for (int v = 0; v < 2; v++)
                #pragma unroll
                for (int mt = 0; mt < 2; mt++) {
                    int r = mt * 16 + rA;
                    unsigned slot = (unsigned)((v * 128 + kseg * 2 + chv) ^ (r & 7));
                    ldm4(pf[v][mt][0], pf[v][mt][1], pf[v][mt][2], pf[v][mt][3],
                         sb + r * 4096 + (slot << 4));
                }
            unsigned bh4[4], bl4[4];
            int krow = s8 * 16 + rA;
            unsigned ob = krow * 128 + ((unsigned)((wn * 2 + chv) ^ (krow & 7)) << 4);
            ldm4t(bh4[0], bh4[1], bh4[2], bh4[3], buf + ob);
            ldm4t(bl4[0], bl4[1], bl4[2], bl4[3], buf + 16384 + ob);
            #pragma unroll
            for (int mt = 0; mt < 2; mt++)
                #pragma unroll
                for (int nt = 0; nt < 2; nt++) {
                    mma_bf16(pacc[mt][nt], pf[0][mt], bh4[nt * 2], bh4[nt * 2 + 1]);
                    mma_bf16(pacc[mt][nt], pf[0][mt], bl4[nt * 2], bl4[nt * 2 + 1]);
                    mma_bf16(pacc[mt][nt], pf[1][mt], bh4[nt * 2], bh4[nt * 2 + 1]);
                }
        }
        __syncthreads();
        if (kt + 2 < 8) load_vt(buf, Vhp, Vlp, kt + 2, tid);
        else asm volatile("cp.async.commit_group;");
    }

    // ---- cross-warp k reduction + hi/lo epilogue ----
    float* red = (float*)(smc + AQB);
    if (wk == 1) {
        #pragma unroll
        for (int mt = 0; mt < 2; mt++)
            #pragma unroll
            for (int nt = 0; nt < 2; nt++) {
                int rr0 = mt * 16 + gr;
                int cc0 = nt * 8 + gc;
                red[wn * 512 + rr0 * 16 + cc0]     = pacc[mt][nt][0];
                red[wn * 512 + rr0 * 16 + cc0 + 1] = pacc[mt][nt][1];
                red[wn * 512 + (rr0 + 8) * 16 + cc0]     = pacc[mt][nt][2];
                red[wn * 512 + (rr0 + 8) * 16 + cc0 + 1] = pacc[mt][nt][3];
            }
    }
    __syncthreads();
    if (wk == 0) {
        #pragma unroll
        for (int mt = 0; mt < 2; mt++)
            #pragma unroll
            for (int nt = 0; nt < 2; nt++) {
                int rr0 = mt * 16 + gr;
                int cc0 = nt * 8 + gc;
                float v0 = pacc[mt][nt][0] + red[wn * 512 + rr0 * 16 + cc0];
                float v1 = pacc[mt][nt][1] + red[wn * 512 + rr0 * 16 + cc0 + 1];
                float v2 = pacc[mt][nt][2] + red[wn * 512 + (rr0 + 8) * 16 + cc0];
                float v3 = pacc[mt][nt][3] + red[wn * 512 + (rr0 + 8) * 16 + cc0 + 1];
                size_t p0 = ((size_t)b * 1024 + q0 + rr0) * 512 + h * 64 + wn * 16 + cc0;
                size_t p1 = p0 + 8 * 512;
                store_hl2(&g_atth[p0], &g_attl[p0], v0, v1);
                store_hl2(&g_atth[p1], &g_attl[p1], v2, v3);
            }
    }
}

// ---------------- launch ----------------
extern "C" void kernel_launch(void* const* d_in, const int* in_sizes, int n_in,
                              void* d_out, int out_size)
{
    (void)in_sizes; (void)n_in; (void)out_size;
    const float* q   = (const float*)d_in[0];
    const float* k   = (const float*)d_in[1];
    const float* v   = (const float*)d_in[2];
    const int*   msk = (const int*)d_in[3];
    const float* Wq  = (const float*)d_in[4];
    const float* Wk  = (const float*)d_in[5];
    const float* Wv  = (const float*)d_in[6];
    const float* Wfc = (const float*)d_in[7];
    const float* g1  = (const float*)d_in[8];
    const float* b1  = (const float*)d_in[9];
    const float* g2  = (const float*)d_in[10];
    const float* b2  = (const float*)d_in[11];
    const float* g3  = (const float*)d_in[12];
    const float* b3  = (const float*)d_in[13];

    float* out = (float*)d_out;
    float* dyn_out  = out;                            // [16,1024,512]
    float* attn_out = out + (size_t)MROWS * 512;      // [128,1024,1024]

    const int gemm_smem = 4 * STG;                    // 131072 B
    const int attn_smem = 204800;                     // 128K S + 64K KV + 8K Q/red
    cudaFuncSetAttribute(gemm_mma_kernel, cudaFuncAttributeMaxDynamicSharedMemorySize, gemm_smem);
    cudaFuncSetAttribute(attn_mma_kernel, cudaFuncAttributeMaxDynamicSharedMemorySize, attn_smem);

    ln_stats_kernel<<<dim3(2048, 3), 256>>>(q, k, v);
    convert_ln_kernel<<<dim3(2048, 3), 256>>>(q, k, v, g1, b1, g2, b2, g3, b3);
    convert_w_kernel<<<1024, 256>>>(Wq, Wk, Wv, Wfc);
    gemm_mma_kernel<<<dim3(4, 128, 3), 256, gemm_smem>>>(nullptr, 0);   // Q,K,V projections
    attn_mma_kernel<<<dim3(32, 128), 256, attn_smem>>>(msk, attn_out);
    gemm_mma_kernel<<<dim3(4, 128, 1), 256, gemm_smem>>>(dyn_out, 1);   // fc
}

// round 7
// speedup vs baseline: 2.5050x; 1.2996x over previous
#include <cuda_runtime.h>
#include <cuda_bf16.h>

#define NB 16
#define NL 1024
#define NH 8
#define MROWS (NB*NL)

// ---------------- scratch ----------------
__device__ float g_mu[3][MROWS];
__device__ float g_rstd[3][MROWS];
__device__ __align__(16) __nv_bfloat16 g_Qh[NB*NH*NL*64];
__device__ __align__(16) __nv_bfloat16 g_Ql[NB*NH*NL*64];
__device__ __align__(16) __nv_bfloat16 g_Kh[NB*NH*NL*64];
__device__ __align__(16) __nv_bfloat16 g_Kl[NB*NH*NL*64];
__device__ __align__(16) __nv_bfloat16 g_Vh[NB*NH*NL*64];
__device__ __align__(16) __nv_bfloat16 g_Vl[NB*NH*NL*64];
__device__ __align__(16) __nv_bfloat16 g_Ah[3][MROWS*512];
__device__ __align__(16) __nv_bfloat16 g_Al[3][MROWS*512];
__device__ __align__(16) __nv_bfloat16 g_Wh[4][512*512];
__device__ __align__(16) __nv_bfloat16 g_Wl[4][512*512];
__device__ __align__(16) __nv_bfloat16 g_atth[MROWS*512];
__device__ __align__(16) __nv_bfloat16 g_attl[MROWS*512];

// ---------------- helpers ----------------
__device__ __forceinline__ unsigned smem_u32(const void* p) {
    unsigned a;
    asm("{ .reg .u64 t; cvta.to.shared.u64 t, %1; cvt.u32.u64 %0, t; }" : "=r"(a) : "l"(p));
    return a;
}
__device__ __forceinline__ void cp16(unsigned dst, const void* src) {
    asm volatile("cp.async.cg.shared.global [%0], [%1], 16;" :: "r"(dst), "l"(src));
}
__device__ __forceinline__ void ldm4(unsigned& r0, unsigned& r1, unsigned& r2, unsigned& r3, unsigned a) {
    asm volatile("ldmatrix.sync.aligned.m8n8.x4.shared.b16 {%0,%1,%2,%3}, [%4];"
                 : "=r"(r0), "=r"(r1), "=r"(r2), "=r"(r3) : "r"(a));
}
__device__ __forceinline__ void ldm2(unsigned& r0, unsigned& r1, unsigned a) {
    asm volatile("ldmatrix.sync.aligned.m8n8.x2.shared.b16 {%0,%1}, [%2];"
                 : "=r"(r0), "=r"(r1) : "r"(a));
}
__device__ __forceinline__ void ldm4t(unsigned& r0, unsigned& r1, unsigned& r2, unsigned& r3, unsigned a) {
    asm volatile("ldmatrix.sync.aligned.m8n8.x4.trans.shared.b16 {%0,%1,%2,%3}, [%4];"
                 : "=r"(r0), "=r"(r1), "=r"(r2), "=r"(r3) : "r"(a));
}
__device__ __forceinline__ void mma_bf16(float* d, const unsigned* a, unsigned b0, unsigned b1) {
    asm volatile(
        "mma.sync.aligned.m16n8k16.row.col.f32.bf16.bf16.f32 "
        "{%0,%1,%2,%3}, {%4,%5,%6,%7}, {%8,%9}, {%0,%1,%2,%3};"
        : "+f"(d[0]), "+f"(d[1]), "+f"(d[2]), "+f"(d[3])
        : "r"(a[0]), "r"(a[1]), "r"(a[2]), "r"(a[3]), "r"(b0), "r"(b1));
}
__device__ __forceinline__ void split_hl(float y, __nv_bfloat16& h, __nv_bfloat16& l) {
    h = __float2bfloat16(y);
    l = __float2bfloat16(y - __bfloat162float(h));
}
__device__ __forceinline__ void store_hl2(__nv_bfloat16* ph, __nv_bfloat16* pl, float a, float b) {
    __nv_bfloat162 H, L;
    split_hl(a, H.x, L.x);
    split_hl(b, H.y, L.y);
    *(__nv_bfloat162*)ph = H;
    *(__nv_bfloat162*)pl = L;
}
__device__ __forceinline__ unsigned pack_hi(float a, float b) {
    __nv_bfloat162 H; H.x = __float2bfloat16(a); H.y = __float2bfloat16(b);
    return *(unsigned*)&H;
}
__device__ __forceinline__ unsigned pack_lo(float a, float b) {
    __nv_bfloat16 ha = __float2bfloat16(a), hb = __float2bfloat16(b);
    __nv_bfloat162 L;
    L.x = __float2bfloat16(a - __bfloat162float(ha));
    L.y = __float2bfloat16(b - __bfloat162float(hb));
    return *(unsigned*)&L;
}

// ---------------- LN stats ----------------
__global__ __launch_bounds__(256) void ln_stats_kernel(
    const float* __restrict__ q, const float* __restrict__ k, const float* __restrict__ v)
{
    int warp = threadIdx.x >> 5, lane = threadIdx.x & 31;
    int row = blockIdx.x * 8 + warp;
    int t = blockIdx.y;
    const float4* x4 = (const float4*)((t == 0 ? q : (t == 1 ? k : v)) + (size_t)row * 512);
    float s = 0.f, ss = 0.f;
    #pragma unroll
    for (int i = 0; i < 4; i++) {
        float4 a = x4[lane + 32 * i];
        s  += a.x + a.y + a.z + a.w;
        ss += a.x*a.x + a.y*a.y + a.z*a.z + a.w*a.w;
    }
    #pragma unroll
    for (int o = 16; o; o >>= 1) {
        s  += __shfl_xor_sync(0xffffffffu, s, o);
        ss += __shfl_xor_sync(0xffffffffu, ss, o);
    }
    if (lane == 0) {
        float mu = s * (1.f / 512.f);
        float var = ss * (1.f / 512.f) - mu * mu;
        g_mu[t][row] = mu;
        g_rstd[t][row] = rsqrtf(var + 1e-5f);
    }
}

// ---------------- LN apply + split ----------------
__global__ __launch_bounds__(256) void convert_ln_kernel(
    const float* __restrict__ q, const float* __restrict__ k, const float* __restrict__ v,
    const float* __restrict__ g1, const float* __restrict__ b1,
    const float* __restrict__ g2, const float* __restrict__ b2,
    const float* __restrict__ g3, const float* __restrict__ b3)
{
    int warp = threadIdx.x >> 5, lane = threadIdx.x & 31;
    int t = blockIdx.y;
    int row = blockIdx.x * 8 + warp;
    const float* x  = (t == 0 ? q  : (t == 1 ? k  : v))  + (size_t)row * 512;
    const float* G  = (t == 0 ? g1 : (t == 1 ? g2 : g3));
    const float* Bt = (t == 0 ? b1 : (t == 1 ? b2 : b3));
    float mu = g_mu[t][row], rs = g_rstd[t][row];
    __nv_bfloat16* ph = g_Ah[t] + (size_t)row * 512;
    __nv_bfloat16* pl = g_Al[t] + (size_t)row * 512;
    #pragma unroll
    for (int i = 0; i < 4; i++) {
        int c4 = lane + 32 * i;
        float4 xv = ((const float4*)x)[c4];
        float4 gv = ((const float4*)G)[c4];
        float4 bv = ((const float4*)Bt)[c4];
        float y[4];
        y[0] = (xv.x - mu) * rs * gv.x + bv.x;
        y[1] = (xv.y - mu) * rs * gv.y + bv.y;
        y[2] = (xv.z - mu) * rs * gv.z + bv.z;
        y[3] = (xv.w - mu) * rs * gv.w + bv.w;
        __nv_bfloat16 hh[4], ll[4];
        #pragma unroll
        for (int j = 0; j < 4; j++) split_hl(y[j], hh[j], ll[j]);
        *(uint2*)(ph + c4 * 4) = *(uint2*)hh;
        *(uint2*)(pl + c4 * 4) = *(uint2*)ll;
    }
}

__global__ __launch_bounds__(256) void convert_w_kernel(
    const float* __restrict__ Wq, const float* __restrict__ Wk,
    const float* __restrict__ Wv, const float* __restrict__ Wfc)
{
    int idx = (blockIdx.x * 256 + threadIdx.x) * 4;
    int mat = idx >> 18;
    int off = idx & 262143;
    const float* W = (mat == 0) ? Wq : ((mat == 1) ? Wk : ((mat == 2) ? Wv : Wfc));
    float4 xv = *(const float4*)(W + off);
    float y[4] = {xv.x, xv.y, xv.z, xv.w};
    __nv_bfloat16 hh[4], ll[4];
    #pragma unroll
    for (int j = 0; j < 4; j++) split_hl(y[j], hh[j], ll[j]);
    *(uint2*)(g_Wh[mat] + off) = *(uint2*)hh;
    *(uint2*)(g_Wl[mat] + off) = *(uint2*)ll;
}

// ---------------- mma.sync GEMM (verbatim from R5 - validated) ----------------
#define STG 32768
#define VOFF_AL 8192
#define VOFF_BH 16384
#define VOFF_BL 24576

__device__ __forceinline__ void load_stage_mma(
    const __nv_bfloat16* __restrict__ Ah, const __nv_bfloat16* __restrict__ Al,
    const __nv_bfloat16* __restrict__ Bh, const __nv_bfloat16* __restrict__ Bl,
    int mr0, int nr0, int kb, unsigned dstb, int tid)
{
    int m = tid >> 1;
    int c = tid & 1;
    unsigned dst0 = dstb + m * 32 + ((unsigned)(c ^ ((m >> 2) & 1)) << 4);
    size_t ga = (size_t)(mr0 + m) * 512 + kb + c * 8;
    size_t gb = (size_t)(nr0 + m) * 512 + kb + c * 8;
    #pragma unroll
    for (int kc = 0; kc < 2; kc++) {
        cp16(dst0 + kc * 4096,           Ah + ga + kc * 16);
        cp16(dst0 + kc * 4096 + VOFF_AL, Al + ga + kc * 16);
        cp16(dst0 + kc * 4096 + VOFF_BH, Bh + gb + kc * 16);
        cp16(dst0 + kc * 4096 + VOFF_BL, Bl + gb + kc * 16);
    }
    asm volatile("cp.async.commit_group;");
}

__global__ __launch_bounds__(256, 1) void gemm_mma_kernel(float* __restrict__ c_fc, int mode)
{
    extern __shared__ char smem[];
    unsigned sb = smem_u32(smem);
    int tid = threadIdx.x, wid = tid >> 5, lane = tid & 31;
    int z = blockIdx.z;
    int mr0 = blockIdx.y * 128;
    int nr0 = blockIdx.x * 128;

    const __nv_bfloat16 *Ah, *Al, *Wh, *Wl;
    __nv_bfloat16 *oh = 0, *ol = 0;
    if (mode == 0) {
        Ah = g_Ah[z]; Al = g_Al[z]; Wh = g_Wh[z]; Wl = g_Wl[z];
        oh = (z == 0) ? g_Qh : ((z == 1) ? g_Kh : g_Vh);
        ol = (z == 0) ? g_Ql : ((z == 1) ? g_Kl : g_Vl);
    } else {
        Ah = g_atth; Al = g_attl; Wh = g_Wh[3]; Wl = g_Wl[3];
    }

    int rA = lane & 15, chv = lane >> 4;
    unsigned offT = (unsigned)(rA * 32 + ((chv ^ ((rA >> 2) & 1)) << 4));
    int wm = wid >> 2, wn = wid & 3;

    float acc[4][4][4];
    #pragma unroll
    for (int a = 0; a < 4; a++)
        #pragma unroll
        for (int b = 0; b < 4; b++)
            #pragma unroll
            for (int c = 0; c < 4; c++) acc[a][b][c] = 0.f;

    load_stage_mma(Ah, Al, Wh, Wl, mr0, nr0, 0,  sb,           tid);
    load_stage_mma(Ah, Al, Wh, Wl, mr0, nr0, 32, sb + STG,     tid);
    load_stage_mma(Ah, Al, Wh, Wl, mr0, nr0, 64, sb + 2 * STG, tid);

    #pragma unroll 1
    for (int s = 0; s < 16; s++) {
        asm volatile("cp.async.wait_group 2;");
        __syncthreads();
        unsigned buf = sb + (unsigned)(s & 3) * STG;

        #pragma unroll
        for (int kc = 0; kc < 2; kc++) {
            unsigned abase = buf + kc * 4096;
            unsigned bbase = buf + VOFF_BH + kc * 4096;
            unsigned aH[4][4], bH[2][4];
            #pragma unroll
            for (int mt = 0; mt < 4; mt++)
                ldm4(aH[mt][0], aH[mt][1], aH[mt][2], aH[mt][3],
                     abase + (unsigned)((wm * 64 + mt * 16) * 32) + offT);
            #pragma unroll
            for (int bt = 0; bt < 2; bt++)
                ldm4(bH[bt][0], bH[bt][1], bH[bt][2], bH[bt][3],
                     bbase + (unsigned)((wn * 32 + bt * 16) * 32) + offT);
            #pragma unroll
            for (int mt = 0; mt < 4; mt++)
                #pragma unroll
                for (int nt = 0; nt < 4; nt++)
                    mma_bf16(acc[mt][nt], aH[mt], bH[nt >> 1][nt & 1], bH[nt >> 1][(nt & 1) + 2]);
            {
                unsigned bL[2][4];
                #pragma unroll
                for (int bt = 0; bt < 2; bt++)
                    ldm4(bL[bt][0], bL[bt][1], bL[bt][2], bL[bt][3],
                         bbase + 8192 + (unsigned)((wn * 32 + bt * 16) * 32) + offT);
                #pragma unroll
                for (int mt = 0; mt < 4; mt++)
                    #pragma unroll
                    for (int nt = 0; nt < 4; nt++)
                        mma_bf16(acc[mt][nt], aH[mt], bL[nt >> 1][nt & 1], bL[nt >> 1][(nt & 1) + 2]);
            }
            {
                unsigned aL[4][4];
                #pragma unroll
                for (int mt = 0; mt < 4; mt++)
                    ldm4(aL[mt][0], aL[mt][1], aL[mt][2], aL[mt][3],
                         abase + VOFF_AL + (unsigned)((wm * 64 + mt * 16) * 32) + offT);
                #pragma unroll
                for (int mt = 0; mt < 4; mt++)
                    #pragma unroll
                    for (int nt = 0; nt < 4; nt++)
                        mma_bf16(acc[mt][nt], aL[mt], bH[nt >> 1][nt & 1], bH[nt >> 1][(nt & 1) + 2]);
            }
        }

        if (s + 3 < 16)
            load_stage_mma(Ah, Al, Wh, Wl, mr0, nr0, (s + 3) * 32, sb + (unsigned)((s + 3) & 3) * STG, tid);
        else
            asm volatile("cp.async.commit_group;");
    }

    int gr = lane >> 2, gc = (lane & 3) * 2;
    #pragma unroll
    for (int mt = 0; mt < 4; mt++) {
        #pragma unroll
        for (int nt = 0; nt < 4; nt++) {
            int r0 = mr0 + wm * 64 + mt * 16 + gr;
            int n0 = nr0 + wn * 32 + nt * 8 + gc;
            if (mode == 0) {
                int h = n0 >> 6, d = n0 & 63;
                int r1 = r0 + 8;
                size_t p0 = ((size_t)((r0 >> 10) * 8 + h) << 16) + (size_t)(r0 & 1023) * 64 + d;
                size_t p1 = ((size_t)((r1 >> 10) * 8 + h) << 16) + (size_t)(r1 & 1023) * 64 + d;
                store_hl2(oh + p0, ol + p0, acc[mt][nt][0], acc[mt][nt][1]);
                store_hl2(oh + p1, ol + p1, acc[mt][nt][2], acc[mt][nt][3]);
            } else {
                float* p0 = c_fc + (size_t)r0 * 512 + n0;
                *(float2*)p0 = make_float2(acc[mt][nt][0], acc[mt][nt][1]);
                *(float2*)(p0 + 8 * 512) = make_float2(acc[mt][nt][2], acc[mt][nt][3]);
            }
        }
    }
}

// ---------------- tensor-core fused attention (512 threads / 16 warps) ----------------
// smem: [0,128K) S fp32 / P bf16 (in place); [128K,192K) K/V dbl buf + reduction; [192K,200K) Q
#define AKB 131072u
#define AQB 196608u

__device__ __forceinline__ void load_kt512(unsigned buf, const __nv_bfloat16* Kh,
                                           const __nv_bfloat16* Kl, int it, int tid)
{
    #pragma unroll
    for (int i = 0; i < 4; i++) {
        int idx = i * 512 + tid;
        int ver = idx >> 10, g = idx & 1023;
        int row = g >> 3, cc = g & 7;
        int kc = cc >> 1, ch = cc & 1;
        unsigned dst = buf + ver * 16384 + kc * 4096 + row * 32
                     + ((unsigned)(ch ^ ((row >> 2) & 1)) << 4);
        cp16(dst, (ver ? Kl : Kh) + (size_t)(it * 128 + row) * 64 + cc * 8);
    }
    asm volatile("cp.async.commit_group;");
}
__device__ __forceinline__ void load_vt512(unsigned buf, const __nv_bfloat16* Vh,
                                           const __nv_bfloat16* Vl, int it, int tid)
{
    #pragma unroll
    for (int i = 0; i < 4; i++) {
        int idx = i * 512 + tid;
        int ver = idx >> 10, g = idx & 1023;
        int row = g >> 3, cc = g & 7;
        unsigned dst = buf + ver * 16384 + row * 128 + ((unsigned)(cc ^ (row & 7)) << 4);
        cp16(dst, (ver ? Vl : Vh) + (size_t)(it * 128 + row) * 64 + cc * 8);
    }
    asm volatile("cp.async.commit_group;");
}

__global__ __launch_bounds__(512, 1) void attn_mma_kernel(
    const int* __restrict__ mask, float* __restrict__ attn_out)
{
    extern __shared__ char smc[];
    unsigned sb = smem_u32(smc);
    float* Ssc = (float*)smc;
    int tid = threadIdx.x, wid = tid >> 5, lane = tid & 31;
    int rA = lane & 15, chv = lane >> 4;
    int gr = lane >> 2, gc = (lane & 3) * 2;
    int q0 = blockIdx.x * 32;
    int bh = blockIdx.y;
    int b = bh >> 3, h = bh & 7;
    const __nv_bfloat16* Qhp = g_Qh + ((size_t)bh << 16) + (size_t)q0 * 64;
    const __nv_bfloat16* Qlp = g_Ql + ((size_t)bh << 16) + (size_t)q0 * 64;
    const __nv_bfloat16* Khp = g_Kh + ((size_t)bh << 16);
    const __nv_bfloat16* Klp = g_Kl + ((size_t)bh << 16);
    const __nv_bfloat16* Vhp = g_Vh + ((size_t)bh << 16);
    const __nv_bfloat16* Vlp = g_Vl + ((size_t)bh << 16);

    // Q tile (rides in K0's commit group): 512 chunks, one per thread
    {
        int ver = tid >> 8, rest = tid & 255;
        int row = rest >> 3, cc = rest & 7;
        int kc = cc >> 1, ch = cc & 1;
        unsigned dst = sb + AQB + ver * 4096 + kc * 1024 + row * 32
                     + ((unsigned)(ch ^ ((row >> 2) & 1)) << 4);
        cp16(dst, (ver ? Qlp : Qhp) + row * 64 + cc * 8);
    }
    load_kt512(sb + AKB, Khp, Klp, 0, tid);
    load_kt512(sb + AKB + 32768, Khp, Klp, 1, tid);

    // ---- pass 1: S = Q K^T / 8 ; warp w covers 8 keys (n0 = w*8) ----
    unsigned qf[2][4][2][4];
    int n0 = wid * 8;
    unsigned offAq[2];
    #pragma unroll
    for (int mt = 0; mt < 2; mt++) {
        int r = mt * 16 + rA;
        offAq[mt] = r * 32 + ((unsigned)(chv ^ ((r >> 2) & 1)) << 4);
    }
    int rB = n0 + (lane & 7);
    int chB = (lane >> 3) & 1;
    unsigned offB = rB * 32 + ((unsigned)(chB ^ ((rB >> 2) & 1)) << 4);

    #pragma unroll 1
    for (int it = 0; it < 8; it++) {
        asm volatile("cp.async.wait_group 1;" ::: "memory");
        __syncthreads();
        unsigned buf = sb + AKB + (unsigned)(it & 1) * 32768;
        if (it == 0) {
            #pragma unroll
            for (int v = 0; v < 2; v++)
                #pragma unroll
                for (int kc = 0; kc < 4; kc++)
                    #pragma unroll
                    for (int mt = 0; mt < 2; mt++)
                        ldm4(qf[v][kc][mt][0], qf[v][kc][mt][1], qf[v][kc][mt][2], qf[v][kc][mt][3],
                             sb + AQB + v * 4096 + kc * 1024 + offAq[mt]);
        }
        float acc[2][4];
        #pragma unroll
        for (int a = 0; a < 2; a++)
            #pragma unroll
            for (int e = 0; e < 4; e++) acc[a][e] = 0.f;
        #pragma unroll
        for (int kc = 0; kc < 4; kc++) {
            unsigned b0h, b1h, b0l, b1l;
            ldm2(b0h, b1h, buf + kc * 4096 + offB);
            ldm2(b0l, b1l, buf + 16384 + kc * 4096 + offB);
            #pragma unroll
            for (int mt = 0; mt < 2; mt++) {
                mma_bf16(acc[mt], qf[0][kc][mt], b0h, b1h);
                mma_bf16(acc[mt], qf[0][kc][mt], b0l, b1l);
                mma_bf16(acc[mt], qf[1][kc][mt], b0h, b1h);
            }
        }
        #pragma unroll
        for (int mt = 0; mt < 2; mt++) {
            int r = mt * 16 + gr;
            int c = it * 128 + n0 + gc;
            unsigned pc0 = (unsigned)c ^ ((unsigned)(r & 7) << 2);
            unsigned pc1 = (unsigned)c ^ ((unsigned)((r + 8) & 7) << 2);
            *(float2*)&Ssc[r * 1024 + pc0] = make_float2(acc[mt][0] * 0.125f, acc[mt][1] * 0.125f);
            *(float2*)&Ssc[(r + 8) * 1024 + pc1] = make_float2(acc[mt][2] * 0.125f, acc[mt][3] * 0.125f);
        }
        __syncthreads();
        if (it + 2 < 8) load_kt512(buf, Khp, Klp, it + 2, tid);
        else asm volatile("cp.async.commit_group;");
    }

    // V tiles 0,1 prefetch (overlaps softmax)
    load_vt512(sb + AKB, Vhp, Vlp, 0, tid);
    load_vt512(sb + AKB + 32768, Vhp, Vlp, 1, tid);

    // ---- register-resident masked softmax + attn write + fused S->P ----
    #pragma unroll 1
    for (int rr = 0; rr < 2; rr++) {
        int r = wid * 2 + rr;
        int qg = q0 + r;
        unsigned xr = (unsigned)(r & 7) << 2;
        const int* mrow = mask + ((size_t)b * 1024 + qg) * 1024;
        float* srow = &Ssc[r * 1024];
        float treg[32];
        float mx = 0.f; int cnt = 0;
        #pragma unroll
        for (int i = 0; i < 16; i++) {
            int kk = lane * 2 + 64 * i;
            float2 s = *(float2*)&srow[(unsigned)kk ^ xr];
            int2 mk = *(const int2*)&mrow[kk];
            bool a0 = (kk != qg) && (mk.x == 0);
            bool a1 = (kk + 1 != qg) && (mk.y == 0);
            float t0 = a0 ? s.x : 0.f;
            float t1 = a1 ? s.y : 0.f;
            treg[2 * i] = t0; treg[2 * i + 1] = t1;
            cnt += (a0 ? 0 : 1) + (a1 ? 0 : 1);
            mx = fmaxf(mx, fmaxf(t0, t1));
        }
        #pragma unroll
        for (int o = 16; o; o >>= 1) {
            mx = fmaxf(mx, __shfl_xor_sync(0xffffffffu, mx, o));
            cnt += __shfl_xor_sync(0xffffffffu, cnt, o);
        }
        float sum = 0.f;
        #pragma unroll
        for (int j = 0; j < 32; j++) {
            float e = (treg[j] != 0.f) ? __expf(treg[j] - mx) : 0.f;
            treg[j] = e;
            sum += e;
        }
        #pragma unroll
        for (int o = 16; o; o >>= 1) sum += __shfl_xor_sync(0xffffffffu, sum, o);
        float Z = sum + (float)cnt * __expf(-mx);
        float inv = 1.f / (sum + 1e-13f * Z);
        float* orow = attn_out + (((size_t)h * NB + b) * 1024 + qg) * 1024;
        #pragma unroll
        for (int i = 0; i < 16; i++) {
            int kk = lane * 2 + 64 * i;
            float a0 = treg[2 * i] * inv, a1 = treg[2 * i + 1] * inv;
            *(float2*)&orow[kk] = make_float2(a0, a1);
            unsigned slot = (unsigned)((kk >> 3) ^ (r & 7));
            unsigned word = ((unsigned)kk >> 1) & 3;
            *(unsigned*)(smc + (size_t)r * 4096 + (slot << 4) + word * 4) = pack_hi(a0, a1);
            *(unsigned*)(smc + (size_t)r * 4096 + (slot << 4) + word * 4 + 2048) = pack_lo(a0, a1);
        }
    }
    __syncthreads();

    // ---- pass 2: out = P V ; 4-way k-split (wk), 4-way n-split (wn) ----
    float pacc[2][2][4];
    #pragma unroll
    for (int a = 0; a < 2; a++)
        #pragma unroll
        for (int c = 0; c < 2; c++)
            #pragma unroll
            for (int e = 0; e < 4; e++) pacc[a][c][e] = 0.f;
    int wk = wid >> 2, wn = wid & 3;

    #pragma unroll 1
    for (int kt = 0; kt < 8; kt++) {
        asm volatile("cp.async.wait_group 1;" ::: "memory");
        __syncthreads();
        unsigned buf = sb + AKB + (unsigned)(kt & 1) * 32768;
        #pragma unroll
        for (int i = 0; i < 2; i++) {
            int s8 = wk * 2 + i;
            int kseg = kt * 8 + s8;
            unsigned pf[2][2][4];
            #pragma unroll
            for (int v = 0; v < 2; v++)
                #pragma unroll
                for (int mt = 0; mt < 2; mt++) {
                    int r = mt * 16 + rA;
                    unsigned slot = (unsigned)((v * 128 + kseg * 2 + chv) ^ (r & 7));
                    ldm4(pf[v][mt][0], pf[v][mt][1], pf[v][mt][2], pf[v][mt][3],
                         sb + r * 4096 + (slot << 4));
                }
            unsigned bh4[4], bl4[4];
            int krow = s8 * 16 + rA;
            unsigned ob = krow * 128 + ((unsigned)((wn * 2 + chv) ^ (krow & 7)) << 4);
            ldm4t(bh4[0], bh4[1], bh4[2], bh4[3], buf + ob);
            ldm4t(bl4[0], bl4[1], bl4[2], bl4[3], buf + 16384 + ob);
            #pragma unroll
            for (int mt = 0; mt < 2; mt++)
                #pragma unroll
                for (int nt = 0; nt < 2; nt++) {
                    mma_bf16(pacc[mt][nt], pf[0][mt], bh4[nt * 2], bh4[nt * 2 + 1]);
                    mma_bf16(pacc[mt][nt], pf[0][mt], bl4[nt * 2], bl4[nt * 2 + 1]);
                    mma_bf16(pacc[mt][nt], pf[1][mt], bh4[nt * 2], bh4[nt * 2 + 1]);
                }
        }
        __syncthreads();
        if (kt + 2 < 8) load_vt512(buf, Vhp, Vlp, kt + 2, tid);
        else asm volatile("cp.async.commit_group;");
    }
    asm volatile("cp.async.wait_group 0;" ::: "memory");
    __syncthreads();

    // ---- cross-warp k reduction (3 partials in freed KV area) + hi/lo epilogue ----
    float* red = (float*)(smc + AKB);    // 3 x 8KB used
    if (wk > 0) {
        int base = (wk - 1) * 2048;
        #pragma unroll
        for (int mt = 0; mt < 2; mt++)
            #pragma unroll
            for (int nt = 0; nt < 2; nt++) {
                int rr0 = mt * 16 + gr;
                int cc0 = wn * 16 + nt * 8 + gc;
                red[base + rr0 * 64 + cc0]     = pacc[mt][nt][0];
                red[base + rr0 * 64 + cc0 + 1] = pacc[mt][nt][1];
                red[base + (rr0 + 8) * 64 + cc0]     = pacc[mt][nt][2];
                red[base + (rr0 + 8) * 64 + cc0 + 1] = pacc[mt][nt][3];
            }
    }
    __syncthreads();
    if (wk == 0) {
        #pragma unroll
        for (int mt = 0; mt < 2; mt++)
            #pragma unroll
            for (int nt = 0; nt < 2; nt++) {
                int rr0 = mt * 16 + gr;
                int cc0 = wn * 16 + nt * 8 + gc;
                float v0 = pacc[mt][nt][0], v1 = pacc[mt][nt][1];
                float v2 = pacc[mt][nt][2], v3 = pacc[mt][nt][3];
                #pragma unroll
                for (int g = 0; g < 3; g++) {
                    v0 += red[g * 2048 + rr0 * 64 + cc0];
                    v1 += red[g * 2048 + rr0 * 64 + cc0 + 1];
                    v2 += red[g * 2048 + (rr0 + 8) * 64 + cc0];
                    v3 += red[g * 2048 + (rr0 + 8) * 64 + cc0 + 1];
                }
                size_t p0 = ((size_t)b * 1024 + q0 + rr0) * 512 + h * 64 + cc0;
                size_t p1 = p0 + 8 * 512;
                store_hl2(&g_atth[p0], &g_attl[p0], v0, v1);
                store_hl2(&g_atth[p1], &g_attl[p1], v2, v3);
            }
    }
}

// ---------------- launch ----------------
extern "C" void kernel_launch(void* const* d_in, const int* in_sizes, int n_in,
                              void* d_out, int out_size)
{
    (void)in_sizes; (void)n_in; (void)out_size;
    const float* q   = (const float*)d_in[0];
    const float* k   = (const float*)d_in[1];
    const float* v   = (const float*)d_in[2];
    const int*   msk = (const int*)d_in[3];
    const float* Wq  = (const float*)d_in[4];
    const float* Wk  = (const float*)d_in[5];
    const float* Wv  = (const float*)d_in[6];
    const float* Wfc = (const float*)d_in[7];
    const float* g1  = (const float*)d_in[8];
    const float* b1  = (const float*)d_in[9];
    const float* g2  = (const float*)d_in[10];
    const float* b2  = (const float*)d_in[11];
    const float* g3  = (const float*)d_in[12];
    const float* b3  = (const float*)d_in[13];

    float* out = (float*)d_out;
    float* dyn_out  = out;                            // [16,1024,512]
    float* attn_out = out + (size_t)MROWS * 512;      // [128,1024,1024]

    const int gemm_smem = 4 * STG;                    // 131072 B
    const int attn_smem = 204800;                     // 128K S + 64K KV + 8K Q
    cudaFuncSetAttribute(gemm_mma_kernel, cudaFuncAttributeMaxDynamicSharedMemorySize, gemm_smem);
    cudaFuncSetAttribute(attn_mma_kernel, cudaFuncAttributeMaxDynamicSharedMemorySize, attn_smem);

    ln_stats_kernel<<<dim3(2048, 3), 256>>>(q, k, v);
    convert_ln_kernel<<<dim3(2048, 3), 256>>>(q, k, v, g1, b1, g2, b2, g3, b3);
    convert_w_kernel<<<1024, 256>>>(Wq, Wk, Wv, Wfc);
    gemm_mma_kernel<<<dim3(4, 128, 3), 256, gemm_smem>>>(nullptr, 0);   // Q,K,V projections
    attn_mma_kernel<<<dim3(32, 128), 512, attn_smem>>>(msk, attn_out);
    gemm_mma_kernel<<<dim3(4, 128, 1), 256, gemm_smem>>>(dyn_out, 1);   // fc
}

// round 8
// speedup vs baseline: 2.5401x; 1.0140x over previous
#include <cuda_runtime.h>
#include <cuda_bf16.h>

#define NB 16
#define NL 1024
#define NH 8
#define MROWS (NB*NL)

// ---------------- scratch ----------------
__device__ float g_mu[3][MROWS];
__device__ float g_rstd[3][MROWS];
__device__ __align__(16) __nv_bfloat16 g_Qh[NB*NH*NL*64];
__device__ __align__(16) __nv_bfloat16 g_Ql[NB*NH*NL*64];
__device__ __align__(16) __nv_bfloat16 g_Kh[NB*NH*NL*64];
__device__ __align__(16) __nv_bfloat16 g_Kl[NB*NH*NL*64];
__device__ __align__(16) __nv_bfloat16 g_Vh[NB*NH*NL*64];
__device__ __align__(16) __nv_bfloat16 g_Vl[NB*NH*NL*64];
__device__ __align__(16) __nv_bfloat16 g_Ah[3][MROWS*512];
__device__ __align__(16) __nv_bfloat16 g_Al[3][MROWS*512];
__device__ __align__(16) __nv_bfloat16 g_Wh[4][512*512];
__device__ __align__(16) __nv_bfloat16 g_Wl[4][512*512];
__device__ __align__(16) __nv_bfloat16 g_atth[MROWS*512];
__device__ __align__(16) __nv_bfloat16 g_attl[MROWS*512];

// ---------------- helpers ----------------
__device__ __forceinline__ unsigned smem_u32(const void* p) {
    unsigned a;
    asm("{ .reg .u64 t; cvta.to.shared.u64 t, %1; cvt.u32.u64 %0, t; }" : "=r"(a) : "l"(p));
    return a;
}
__device__ __forceinline__ void cp16(unsigned dst, const void* src) {
    asm volatile("cp.async.cg.shared.global [%0], [%1], 16;" :: "r"(dst), "l"(src));
}
__device__ __forceinline__ void ldm4(unsigned& r0, unsigned& r1, unsigned& r2, unsigned& r3, unsigned a) {
    asm volatile("ldmatrix.sync.aligned.m8n8.x4.shared.b16 {%0,%1,%2,%3}, [%4];"
                 : "=r"(r0), "=r"(r1), "=r"(r2), "=r"(r3) : "r"(a));
}
__device__ __forceinline__ void ldm2(unsigned& r0, unsigned& r1, unsigned a) {
    asm volatile("ldmatrix.sync.aligned.m8n8.x2.shared.b16 {%0,%1}, [%2];"
                 : "=r"(r0), "=r"(r1) : "r"(a));
}
__device__ __forceinline__ void ldm4t(unsigned& r0, unsigned& r1, unsigned& r2, unsigned& r3, unsigned a) {
    asm volatile("ldmatrix.sync.aligned.m8n8.x4.trans.shared.b16 {%0,%1,%2,%3}, [%4];"
                 : "=r"(r0), "=r"(r1), "=r"(r2), "=r"(r3) : "r"(a));
}
__device__ __forceinline__ void mma_bf16(float* d, const unsigned* a, unsigned b0, unsigned b1) {
    asm volatile(
        "mma.sync.aligned.m16n8k16.row.col.f32.bf16.bf16.f32 "
        "{%0,%1,%2,%3}, {%4,%5,%6,%7}, {%8,%9}, {%0,%1,%2,%3};"
        : "+f"(d[0]), "+f"(d[1]), "+f"(d[2]), "+f"(d[3])
        : "r"(a[0]), "r"(a[1]), "r"(a[2]), "r"(a[3]), "r"(b0), "r"(b1));
}
__device__ __forceinline__ void split_hl(float y, __nv_bfloat16& h, __nv_bfloat16& l) {
    h = __float2bfloat16(y);
    l = __float2bfloat16(y - __bfloat162float(h));
}
__device__ __forceinline__ void store_hl2(__nv_bfloat16* ph, __nv_bfloat16* pl, float a, float b) {
    __nv_bfloat162 H, L;
    split_hl(a, H.x, L.x);
    split_hl(b, H.y, L.y);
    *(__nv_bfloat162*)ph = H;
    *(__nv_bfloat162*)pl = L;
}
__device__ __forceinline__ unsigned pack_hi(float a, float b) {
    __nv_bfloat162 H; H.x = __float2bfloat16(a); H.y = __float2bfloat16(b);
    return *(unsigned*)&H;
}
__device__ __forceinline__ unsigned pack_lo(float a, float b) {
    __nv_bfloat16 ha = __float2bfloat16(a), hb = __float2bfloat16(b);
    __nv_bfloat162 L;
    L.x = __float2bfloat16(a - __bfloat162float(ha));
    L.y = __float2bfloat16(b - __bfloat162float(hb));
    return *(unsigned*)&L;
}

// ---------------- LN stats ----------------
__global__ __launch_bounds__(256) void ln_stats_kernel(
    const float* __restrict__ q, const float* __restrict__ k, const float* __restrict__ v)
{
    int warp = threadIdx.x >> 5, lane = threadIdx.x & 31;
    int row = blockIdx.x * 8 + warp;
    int t = blockIdx.y;
    const float4* x4 = (const float4*)((t == 0 ? q : (t == 1 ? k : v)) + (size_t)row * 512);
    float s = 0.f, ss = 0.f;
    #pragma unroll
    for (int i = 0; i < 4; i++) {
        float4 a = x4[lane + 32 * i];
        s  += a.x + a.y + a.z + a.w;
        ss += a.x*a.x + a.y*a.y + a.z*a.z + a.w*a.w;
    }
    #pragma unroll
    for (int o = 16; o; o >>= 1) {
        s  += __shfl_xor_sync(0xffffffffu, s, o);
        ss += __shfl_xor_sync(0xffffffffu, ss, o);
    }
    if (lane == 0) {
        float mu = s * (1.f / 512.f);
        float var = ss * (1.f / 512.f) - mu * mu;
        g_mu[t][row] = mu;
        g_rstd[t][row] = rsqrtf(var + 1e-5f);
    }
}

// ---------------- LN apply + split ----------------
__global__ __launch_bounds__(256) void convert_ln_kernel(
    const float* __restrict__ q, const float* __restrict__ k, const float* __restrict__ v,
    const float* __restrict__ g1, const float* __restrict__ b1,
    const float* __restrict__ g2, const float* __restrict__ b2,
    const float* __restrict__ g3, const float* __restrict__ b3)
{
    int warp = threadIdx.x >> 5, lane = threadIdx.x & 31;
    int t = blockIdx.y;
    int row = blockIdx.x * 8 + warp;
    const float* x  = (t == 0 ? q  : (t == 1 ? k  : v))  + (size_t)row * 512;
    const float* G  = (t == 0 ? g1 : (t == 1 ? g2 : g3));
    const float* Bt = (t == 0 ? b1 : (t == 1 ? b2 : b3));
    float mu = g_mu[t][row], rs = g_rstd[t][row];
    __nv_bfloat16* ph = g_Ah[t] + (size_t)row * 512;
    __nv_bfloat16* pl = g_Al[t] + (size_t)row * 512;
    #pragma unroll
    for (int i = 0; i < 4; i++) {
        int c4 = lane + 32 * i;
        float4 xv = ((const float4*)x)[c4];
        float4 gv = ((const float4*)G)[c4];
        float4 bv = ((const float4*)Bt)[c4];
        float y[4];
        y[0] = (xv.x - mu) * rs * gv.x + bv.x;
        y[1] = (xv.y - mu) * rs * gv.y + bv.y;
        y[2] = (xv.z - mu) * rs * gv.z + bv.z;
        y[3] = (xv.w - mu) * rs * gv.w + bv.w;
        __nv_bfloat16 hh[4], ll[4];
        #pragma unroll
        for (int j = 0; j < 4; j++) split_hl(y[j], hh[j], ll[j]);
        *(uint2*)(ph + c4 * 4) = *(uint2*)hh;
        *(uint2*)(pl + c4 * 4) = *(uint2*)ll;
    }
}

__global__ __launch_bounds__(256) void convert_w_kernel(
    const float* __restrict__ Wq, const float* __restrict__ Wk,
    const float* __restrict__ Wv, const float* __restrict__ Wfc)
{
    int idx = (blockIdx.x * 256 + threadIdx.x) * 4;
    int mat = idx >> 18;
    int off = idx & 262143;
    const float* W = (mat == 0) ? Wq : ((mat == 1) ? Wk : ((mat == 2) ? Wv : Wfc));
    float4 xv = *(const float4*)(W + off);
    float y[4] = {xv.x, xv.y, xv.z, xv.w};
    __nv_bfloat16 hh[4], ll[4];
    #pragma unroll
    for (int j = 0; j < 4; j++) split_hl(y[j], hh[j], ll[j]);
    *(uint2*)(g_Wh[mat] + off) = *(uint2*)hh;
    *(uint2*)(g_Wl[mat] + off) = *(uint2*)ll;
}

// ---------------- mma.sync GEMM: 512 threads, 16 warps, 32x32 warp tile ----------------
// BM=BN=128, BK=32. Stage smem: Ah 8K | Al 8K | Bh 8K | Bl 8K = 32KB, 4 stages.
#define STG 32768
#define VOFF_AL 8192
#define VOFF_BH 16384
#define VOFF_BL 24576

__device__ __forceinline__ void load_stage_mma(
    const __nv_bfloat16* __restrict__ Ah, const __nv_bfloat16* __restrict__ Al,
    const __nv_bfloat16* __restrict__ Bh, const __nv_bfloat16* __restrict__ Bl,
    int mr0, int nr0, int kb, unsigned dstb, int tid)
{
    int m = tid >> 2;          // 0..127
    int cc = tid & 3;
    int kc = cc >> 1, c = cc & 1;
    unsigned dst = dstb + kc * 4096 + m * 32 + ((unsigned)(c ^ ((m >> 2) & 1)) << 4);
    size_t ga = (size_t)(mr0 + m) * 512 + kb + kc * 16 + c * 8;
    size_t gb = (size_t)(nr0 + m) * 512 + kb + kc * 16 + c * 8;
    cp16(dst,           Ah + ga);
    cp16(dst + VOFF_AL, Al + ga);
    cp16(dst + VOFF_BH, Bh + gb);
    cp16(dst + VOFF_BL, Bl + gb);
    asm volatile("cp.async.commit_group;");
}

__global__ __launch_bounds__(512, 1) void gemm_mma_kernel(float* __restrict__ c_fc, int mode)
{
    extern __shared__ char smem[];
    unsigned sb = smem_u32(smem);
    int tid = threadIdx.x, wid = tid >> 5, lane = tid & 31;
    int z = blockIdx.z;
    int mr0 = blockIdx.y * 128;
    int nr0 = blockIdx.x * 128;

    const __nv_bfloat16 *Ah, *Al, *Wh, *Wl;
    __nv_bfloat16 *oh = 0, *ol = 0;
    if (mode == 0) {
        Ah = g_Ah[z]; Al = g_Al[z]; Wh = g_Wh[z]; Wl = g_Wl[z];
        oh = (z == 0) ? g_Qh : ((z == 1) ? g_Kh : g_Vh);
        ol = (z == 0) ? g_Ql : ((z == 1) ? g_Kl : g_Vl);
    } else {
        Ah = g_atth; Al = g_attl; Wh = g_Wh[3]; Wl = g_Wl[3];
    }

    int rA = lane & 15, chv = lane >> 4;
    unsigned offT = (unsigned)(rA * 32 + ((chv ^ ((rA >> 2) & 1)) << 4));
    int wm = wid >> 2, wn = wid & 3;   // warp tile: rows wm*32, cols wn*32

    float acc[2][4][4];
    #pragma unroll
    for (int a = 0; a < 2; a++)
        #pragma unroll
        for (int b = 0; b < 4; b++)
            #pragma unroll
            for (int c = 0; c < 4; c++) acc[a][b][c] = 0.f;

    load_stage_mma(Ah, Al, Wh, Wl, mr0, nr0, 0,  sb,           tid);
    load_stage_mma(Ah, Al, Wh, Wl, mr0, nr0, 32, sb + STG,     tid);
    load_stage_mma(Ah, Al, Wh, Wl, mr0, nr0, 64, sb + 2 * STG, tid);

    #pragma unroll 1
    for (int s = 0; s < 16; s++) {
        asm volatile("cp.async.wait_group 2;");
        __syncthreads();
        unsigned buf = sb + (unsigned)(s & 3) * STG;

        #pragma unroll
        for (int kc = 0; kc < 2; kc++) {
            unsigned abase = buf + kc * 4096;
            unsigned bbase = buf + VOFF_BH + kc * 4096;
            unsigned aH[2][4], bH[2][4];
            #pragma unroll
            for (int mt = 0; mt < 2; mt++)
                ldm4(aH[mt][0], aH[mt][1], aH[mt][2], aH[mt][3],
                     abase + (unsigned)((wm * 32 + mt * 16) * 32) + offT);
            #pragma unroll
            for (int bt = 0; bt < 2; bt++)
                ldm4(bH[bt][0], bH[bt][1], bH[bt][2], bH[bt][3],
                     bbase + (unsigned)((wn * 32 + bt * 16) * 32) + offT);
            // pass 1: Ah * Bh
            #pragma unroll
            for (int mt = 0; mt < 2; mt++)
                #pragma unroll
                for (int nt = 0; nt < 4; nt++)
                    mma_bf16(acc[mt][nt], aH[mt], bH[nt >> 1][nt & 1], bH[nt >> 1][(nt & 1) + 2]);
            // pass 2: Ah * Bl
            {
                unsigned bL[2][4];
                #pragma unroll
                for (int bt = 0; bt < 2; bt++)
                    ldm4(bL[bt][0], bL[bt][1], bL[bt][2], bL[bt][3],
                         bbase + 8192 + (unsigned)((wn * 32 + bt * 16) * 32) + offT);
                #pragma unroll
                for (int mt = 0; mt < 2; mt++)
                    #pragma unroll
                    for (int nt = 0; nt < 4; nt++)
                        mma_bf16(acc[mt][nt], aH[mt], bL[nt >> 1][nt & 1], bL[nt >> 1][(nt & 1) + 2]);
            }
            // pass 3: Al * Bh
            {
                unsigned aL[2][4];
                #pragma unroll
                for (int mt = 0; mt < 2; mt++)
                    ldm4(aL[mt][0], aL[mt][1], aL[mt][2], aL[mt][3],
                         abase + VOFF_AL + (unsigned)((wm * 32 + mt * 16) * 32) + offT);
                #pragma unroll
                for (int mt = 0; mt < 2; mt++)
                    #pragma unroll
                    for (int nt = 0; nt < 4; nt++)
                        mma_bf16(acc[mt][nt], aL[mt], bH[nt >> 1][nt & 1], bH[nt >> 1][(nt & 1) + 2]);
            }
        }

        if (s + 3 < 16)
            load_stage_mma(Ah, Al, Wh, Wl, mr0, nr0, (s + 3) * 32, sb + (unsigned)((s + 3) & 3) * STG, tid);
        else
            asm volatile("cp.async.commit_group;");
    }

    int gr = lane >> 2, gc = (lane & 3) * 2;
    #pragma unroll
    for (int mt = 0; mt < 2; mt++) {
        #pragma unroll
        for (int nt = 0; nt < 4; nt++) {
            int r0 = mr0 + wm * 32 + mt * 16 + gr;
            int n0 = nr0 + wn * 32 + nt * 8 + gc;
            if (mode == 0) {
                int h = n0 >> 6, d = n0 & 63;
                int r1 = r0 + 8;
                size_t p0 = ((size_t)((r0 >> 10) * 8 + h) << 16) + (size_t)(r0 & 1023) * 64 + d;
                size_t p1 = ((size_t)((r1 >> 10) * 8 + h) << 16) + (size_t)(r1 & 1023) * 64 + d;
                store_hl2(oh + p0, ol + p0, acc[mt][nt][0], acc[mt][nt][1]);
                store_hl2(oh + p1, ol + p1, acc[mt][nt][2], acc[mt][nt][3]);
            } else {
                float* p0 = c_fc + (size_t)r0 * 512 + n0;
                *(float2*)p0 = make_float2(acc[mt][nt][0], acc[mt][nt][1]);
                *(float2*)(p0 + 8 * 512) = make_float2(acc[mt][nt][2], acc[mt][nt][3]);
            }
        }
    }
}

// ---------------- tensor-core fused attention (verbatim from R6 - validated) ----------------
#define AKB 131072u
#define AQB 196608u

__device__ __forceinline__ void load_kt512(unsigned buf, const __nv_bfloat16* Kh,
                                           const __nv_bfloat16* Kl, int it, int tid)
{
    #pragma unroll
    for (int i = 0; i < 4; i++) {
        int idx = i * 512 + tid;
        int ver = idx >> 10, g = idx & 1023;
        int row = g >> 3, cc = g & 7;
        int kc = cc >> 1, ch = cc & 1;
        unsigned dst = buf + ver * 16384 + kc * 4096 + row * 32
                     + ((unsigned)(ch ^ ((row >> 2) & 1)) << 4);
        cp16(dst, (ver ? Kl : Kh) + (size_t)(it * 128 + row) * 64 + cc * 8);
    }
    asm volatile("cp.async.commit_group;");
}
__device__ __forceinline__ void load_vt512(unsigned buf, const __nv_bfloat16* Vh,
                                           const __nv_bfloat16* Vl, int it, int tid)
{
    #pragma unroll
    for (int i = 0; i < 4; i++) {
        int idx = i * 512 + tid;
        int ver = idx >> 10, g = idx & 1023;
        int row = g >> 3, cc = g & 7;
        unsigned dst = buf + ver * 16384 + row * 128 + ((unsigned)(cc ^ (row & 7)) << 4);
        cp16(dst, (ver ? Vl : Vh) + (size_t)(it * 128 + row) * 64 + cc * 8);
    }
    asm volatile("cp.async.commit_group;");
}

__global__ __launch_bounds__(512, 1) void attn_mma_kernel(
    const int* __restrict__ mask, float* __restrict__ attn_out)
{
    extern __shared__ char smc[];
    unsigned sb = smem_u32(smc);
    float* Ssc = (float*)smc;
    int tid = threadIdx.x, wid = tid >> 5, lane = tid & 31;
    int rA = lane & 15, chv = lane >> 4;
    int gr = lane >> 2, gc = (lane & 3) * 2;
    int q0 = blockIdx.x * 32;
    int bh = blockIdx.y;
    int b = bh >> 3, h = bh & 7;
    const __nv_bfloat16* Qhp = g_Qh + ((size_t)bh << 16) + (size_t)q0 * 64;
    const __nv_bfloat16* Qlp = g_Ql + ((size_t)bh << 16) + (size_t)q0 * 64;
    const __nv_bfloat16* Khp = g_Kh + ((size_t)bh << 16);
    const __nv_bfloat16* Klp = g_Kl + ((size_t)bh << 16);
    const __nv_bfloat16* Vhp = g_Vh + ((size_t)bh << 16);
    const __nv_bfloat16* Vlp = g_Vl + ((size_t)bh << 16);

    {
        int ver = tid >> 8, rest = tid & 255;
        int row = rest >> 3, cc = rest & 7;
        int kc = cc >> 1, ch = cc & 1;
        unsigned dst = sb + AQB + ver * 4096 + kc * 1024 + row * 32
                     + ((unsigned)(ch ^ ((row >> 2) & 1)) << 4);
        cp16(dst, (ver ? Qlp : Qhp) + row * 64 + cc * 8);
    }
    load_kt512(sb + AKB, Khp, Klp, 0, tid);
    load_kt512(sb + AKB + 32768, Khp, Klp, 1, tid);

    unsigned qf[2][4][2][4];
    int n0 = wid * 8;
    unsigned offAq[2];
    #pragma unroll
    for (int mt = 0; mt < 2; mt++) {
        int r = mt * 16 + rA;
        offAq[mt] = r * 32 + ((unsigned)(chv ^ ((r >> 2) & 1)) << 4);
    }
    int rB = n0 + (lane & 7);
    int chB = (lane >> 3) & 1;
    unsigned offB = rB * 32 + ((unsigned)(chB ^ ((rB >> 2) & 1)) << 4);

    #pragma unroll 1
    for (int it = 0; it < 8; it++) {
        asm volatile("cp.async.wait_group 1;" ::: "memory");
        __syncthreads();
        unsigned buf = sb + AKB + (unsigned)(it & 1) * 32768;
        if (it == 0) {
            #pragma unroll
            for (int v = 0; v < 2; v++)
                #pragma unroll
                for (int kc = 0; kc < 4; kc++)
                    #pragma unroll
                    for (int mt = 0; mt < 2; mt++)
                        ldm4(qf[v][kc][mt][0], qf[v][kc][mt][1], qf[v][kc][mt][2], qf[v][kc][mt][3],
                             sb + AQB + v * 4096 + kc * 1024 + offAq[mt]);
        }
        float acc[2][4];
        #pragma unroll
        for (int a = 0; a < 2; a++)
            #pragma unroll
            for (int e = 0; e < 4; e++) acc[a][e] = 0.f;
        #pragma unroll
        for (int kc = 0; kc < 4; kc++) {
            unsigned b0h, b1h, b0l, b1l;
            ldm2(b0h, b1h, buf + kc * 4096 + offB);
            ldm2(b0l, b1l, buf + 16384 + kc * 4096 + offB);
            #pragma unroll
            for (int mt = 0; mt < 2; mt++) {
                mma_bf16(acc[mt], qf[0][kc][mt], b0h, b1h);
                mma_bf16(acc[mt], qf[0][kc][mt], b0l, b1l);
                mma_bf16(acc[mt], qf[1][kc][mt], b0h, b1h);
            }
        }
        #pragma unroll
        for (int mt = 0; mt < 2; mt++) {
            int r = mt * 16 + gr;
            int c = it * 128 + n0 + gc;
            unsigned pc0 = (unsigned)c ^ ((unsigned)(r & 7) << 2);
            unsigned pc1 = (unsigned)c ^ ((unsigned)((r + 8) & 7) << 2);
            *(float2*)&Ssc[r * 1024 + pc0] = make_float2(acc[mt][0] * 0.125f, acc[mt][1] * 0.125f);
            *(float2*)&Ssc[(r + 8) * 1024 + pc1] = make_float2(acc[mt][2] * 0.125f, acc[mt][3] * 0.125f);
        }
        __syncthreads();
        if (it + 2 < 8) load_kt512(buf, Khp, Klp, it + 2, tid);
        else asm volatile("cp.async.commit_group;");
    }

    load_vt512(sb + AKB, Vhp, Vlp, 0, tid);
    load_vt512(sb + AKB + 32768, Vhp, Vlp, 1, tid);

    #pragma unroll 1
    for (int rr = 0; rr < 2; rr++) {
        int r = wid * 2 + rr;
        int qg = q0 + r;
        unsigned xr = (unsigned)(r & 7) << 2;
        const int* mrow = mask + ((size_t)b * 1024 + qg) * 1024;
        float* srow = &Ssc[r * 1024];
        float treg[32];
        float mx = 0.f; int cnt = 0;
        #pragma unroll
        for (int i = 0; i < 16; i++) {
            int kk = lane * 2 + 64 * i;
            float2 s = *(float2*)&srow[(unsigned)kk ^ xr];
            int2 mk = *(const int2*)&mrow[kk];
            bool a0 = (kk != qg) && (mk.x == 0);
            bool a1 = (kk + 1 != qg) && (mk.y == 0);
            float t0 = a0 ? s.x : 0.f;
            float t1 = a1 ? s.y : 0.f;
            treg[2 * i] = t0; treg[2 * i + 1] = t1;
            cnt += (a0 ? 0 : 1) + (a1 ? 0 : 1);
            mx = fmaxf(mx, fmaxf(t0, t1));
        }
        #pragma unroll
        for (int o = 16; o; o >>= 1) {
            mx = fmaxf(mx, __shfl_xor_sync(0xffffffffu, mx, o));
            cnt += __shfl_xor_sync(0xffffffffu, cnt, o);
        }
        float sum = 0.f;
        #pragma unroll
        for (int j = 0; j < 32; j++) {
            float e = (treg[j] != 0.f) ? __expf(treg[j] - mx) : 0.f;
            treg[j] = e;
            sum += e;
        }
        #pragma unroll
        for (int o = 16; o; o >>= 1) sum += __shfl_xor_sync(0xffffffffu, sum, o);
        float Z = sum + (float)cnt * __expf(-mx);
        float inv = 1.f / (sum + 1e-13f * Z);
        float* orow = attn_out + (((size_t)h * NB + b) * 1024 + qg) * 1024;
        #pragma unroll
        for (int i = 0; i < 16; i++) {
            int kk = lane * 2 + 64 * i;
            float a0 = treg[2 * i] * inv, a1 = treg[2 * i + 1] * inv;
            *(float2*)&orow[kk] = make_float2(a0, a1);
            unsigned slot = (unsigned)((kk >> 3) ^ (r & 7));
            unsigned word = ((unsigned)kk >> 1) & 3;
            *(unsigned*)(smc + (size_t)r * 4096 + (slot << 4) + word * 4) = pack_hi(a0, a1);
            *(unsigned*)(smc + (size_t)r * 4096 + (slot << 4) + word * 4 + 2048) = pack_lo(a0, a1);
        }
    }
    __syncthreads();

    float pacc[2][2][4];
    #pragma unroll
    for (int a = 0; a < 2; a++)
        #pragma unroll
        for (int c = 0; c < 2; c++)
            #pragma unroll
            for (int e = 0; e < 4; e++) pacc[a][c][e] = 0.f;
    int wk = wid >> 2, wn = wid & 3;

    #pragma unroll 1
    for (int kt = 0; kt < 8; kt++) {
        asm volatile("cp.async.wait_group 1;" ::: "memory");
        __syncthreads();
        unsigned buf = sb + AKB + (unsigned)(kt & 1) * 32768;
        #pragma unroll
        for (int i = 0; i < 2; i++) {
            int s8 = wk * 2 + i;
            int kseg = kt * 8 + s8;
            unsigned pf[2][2][4];
            #pragma unroll
            for (int v = 0; v < 2; v++)
                #pragma unroll
                for (int mt = 0; mt < 2; mt++) {
                    int r = mt * 16 + rA;
                    unsigned slot = (unsigned)((v * 128 + kseg * 2 + chv) ^ (r & 7));
                    ldm4(pf[v][mt][0], pf[v][mt][1], pf[v][mt][2], pf[v][mt][3],
                         sb + r * 4096 + (slot << 4));
                }
            unsigned bh4[4], bl4[4];
            int krow = s8 * 16 + rA;
            unsigned ob = krow * 128 + ((unsigned)((wn * 2 + chv) ^ (krow & 7)) << 4);
            ldm4t(bh4[0], bh4[1], bh4[2], bh4[3], buf + ob);
            ldm4t(bl4[0], bl4[1], bl4[2], bl4[3], buf + 16384 + ob);
            #pragma unroll
            for (int mt = 0; mt < 2; mt++)
                #pragma unroll
                for (int nt = 0; nt < 2; nt++) {
                    mma_bf16(pacc[mt][nt], pf[0][mt], bh4[nt * 2], bh4[nt * 2 + 1]);
                    mma_bf16(pacc[mt][nt], pf[0][mt], bl4[nt * 2], bl4[nt * 2 + 1]);
                    mma_bf16(pacc[mt][nt], pf[1][mt], bh4[nt * 2], bh4[nt * 2 + 1]);
                }
        }
        __syncthreads();
        if (kt + 2 < 8) load_vt512(buf, Vhp, Vlp, kt + 2, tid);
        else asm volatile("cp.async.commit_group;");
    }
    asm volatile("cp.async.wait_group 0;" ::: "memory");
    __syncthreads();

    float* red = (float*)(smc + AKB);
    if (wk > 0) {
        int base = (wk - 1) * 2048;
        #pragma unroll
        for (int mt = 0; mt < 2; mt++)
            #pragma unroll
            for (int nt = 0; nt < 2; nt++) {
                int rr0 = mt * 16 + gr;
                int cc0 = wn * 16 + nt * 8 + gc;
                red[base + rr0 * 64 + cc0]     = pacc[mt][nt][0];
                red[base + rr0 * 64 + cc0 + 1] = pacc[mt][nt][1];
                red[base + (rr0 + 8) * 64 + cc0]     = pacc[mt][nt][2];
                red[base + (rr0 + 8) * 64 + cc0 + 1] = pacc[mt][nt][3];
            }
    }
    __syncthreads();
    if (wk == 0) {
        #pragma unroll
        for (int mt = 0; mt < 2; mt++)
            #pragma unroll
            for (int nt = 0; nt < 2; nt++) {
                int rr0 = mt * 16 + gr;
                int cc0 = wn * 16 + nt * 8 + gc;
                float v0 = pacc[mt][nt][0], v1 = pacc[mt][nt][1];
                float v2 = pacc[mt][nt][2], v3 = pacc[mt][nt][3];
                #pragma unroll
                for (int g = 0; g < 3; g++) {
                    v0 += red[g * 2048 + rr0 * 64 + cc0];
                    v1 += red[g * 2048 + rr0 * 64 + cc0 + 1];
                    v2 += red[g * 2048 + (rr0 + 8) * 64 + cc0];
                    v3 += red[g * 2048 + (rr0 + 8) * 64 + cc0 + 1];
                }
                size_t p0 = ((size_t)b * 1024 + q0 + rr0) * 512 + h * 64 + cc0;
                size_t p1 = p0 + 8 * 512;
                store_hl2(&g_atth[p0], &g_attl[p0], v0, v1);
                store_hl2(&g_atth[p1], &g_attl[p1], v2, v3);
            }
    }
}

// ---------------- launch ----------------
extern "C" void kernel_launch(void* const* d_in, const int* in_sizes, int n_in,
                              void* d_out, int out_size)
{
    (void)in_sizes; (void)n_in; (void)out_size;
    const float* q   = (const float*)d_in[0];
    const float* k   = (const float*)d_in[1];
    const float* v   = (const float*)d_in[2];
    const int*   msk = (const int*)d_in[3];
    const float* Wq  = (const float*)d_in[4];
    const float* Wk  = (const float*)d_in[5];
    const float* Wv  = (const float*)d_in[6];
    const float* Wfc = (const float*)d_in[7];
    const float* g1  = (const float*)d_in[8];
    const float* b1  = (const float*)d_in[9];
    const float* g2  = (const float*)d_in[10];
    const float* b2  = (const float*)d_in[11];
    const float* g3  = (const float*)d_in[12];
    const float* b3  = (const float*)d_in[13];

    float* out = (float*)d_out;
    float* dyn_out  = out;                            // [16,1024,512]
    float* attn_out = out + (size_t)MROWS * 512;      // [128,1024,1024]

    const int gemm_smem = 4 * STG;                    // 131072 B
    const int attn_smem = 204800;                     // 128K S + 64K KV + 8K Q
    cudaFuncSetAttribute(gemm_mma_kernel, cudaFuncAttributeMaxDynamicSharedMemorySize, gemm_smem);
    cudaFuncSetAttribute(attn_mma_kernel, cudaFuncAttributeMaxDynamicSharedMemorySize, attn_smem);

    ln_stats_kernel<<<dim3(2048, 3), 256>>>(q, k, v);
    convert_ln_kernel<<<dim3(2048, 3), 256>>>(q, k, v, g1, b1, g2, b2, g3, b3);
    convert_w_kernel<<<1024, 256>>>(Wq, Wk, Wv, Wfc);
    gemm_mma_kernel<<<dim3(4, 128, 3), 512, gemm_smem>>>(nullptr, 0);   // Q,K,V projections
    attn_mma_kernel<<<dim3(32, 128), 512, attn_smem>>>(msk, attn_out);
    gemm_mma_kernel<<<dim3(4, 128, 1), 512, gemm_smem>>>(dyn_out, 1);   // fc
}